// round 1
// baseline (speedup 1.0000x reference)
#include <cuda_runtime.h>
#include <math.h>
#include <stdint.h>

// Problem constants
#define BATCH 8
#define CHN   64
#define PIX   1024
#define PQ    256
#define GRP   32
#define HW    16384   // 128*128
#define KTOP  21      // int(32/3*2)

// ---------------- scratch (static device globals; no allocation) ----------------
__device__ float d_pooled[BATCH*CHN*PIX];   // [(b*64+c)*1024 + p]
__device__ float d_xpre  [BATCH*GRP*PIX];   // [(b*32+g)*1024 + p]
__device__ float d_qg    [BATCH*GRP*PQ];    // [(b*32+s)*256 + d]
__device__ float d_kg    [BATCH*GRP*PQ];
__device__ float d_adj   [BATCH*GRP*GRP];   // [(b*32+s)*32 + t]
__device__ float d_v     [BATCH*GRP*PIX];
__device__ float d_av    [BATCH*GRP*PIX];   // adj @ v
__device__ float d_gcnout[BATCH*GRP*PIX];
__device__ float d_value [BATCH*GRP*PIX];
__device__ float d_q2    [BATCH*GRP*PQ];
__device__ float d_key   [BATCH*CHN*PQ];    // [(b*64+c)*256 + d]
__device__ float d_atten [BATCH*CHN*GRP];   // [(b*64+c)*32 + g]
__device__ float d_tuT   [BATCH*PIX*CHN];   // [b*65536 + p*64 + c] = tu[b,c,p]
__device__ float d_Gpart [BATCH*8*CHN*CHN]; // per-k-chunk partial Gram
__device__ float d_G     [BATCH*CHN*CHN];   // [b*4096 + c1*64 + c2]

// ---------------- warp helpers ----------------
__device__ __forceinline__ float wmax(float v) {
    #pragma unroll
    for (int o = 16; o > 0; o >>= 1) v = fmaxf(v, __shfl_xor_sync(0xffffffffu, v, o));
    return v;
}
__device__ __forceinline__ float wsum(float v) {
    #pragma unroll
    for (int o = 16; o > 0; o >>= 1) v += __shfl_xor_sync(0xffffffffu, v, o);
    return v;
}

// ---------------- 1. 4x4 mean pool: x[8,64,128,128] -> pooled[8,64,1024] ----------------
__global__ void __launch_bounds__(256) pool_k(const float* __restrict__ x)
{
    const int bc = blockIdx.x;                       // b*64+c
    const float* xp = x + (size_t)bc * HW;
    for (int p = threadIdx.x; p < PIX; p += 256) {
        const int h4 = p >> 5, w4 = p & 31;
        const float* base = xp + (h4 * 4) * 128 + w4 * 4;
        float s = 0.f;
        #pragma unroll
        for (int i = 0; i < 4; i++) {
            float4 r = *(const float4*)(base + i * 128);
            s += r.x + r.y + r.z + r.w;
        }
        d_pooled[bc * PIX + p] = s * (1.f / 16.f);
    }
}

// ---------------- 2. xpre[b,g,p] = mean of channel pair ----------------
__global__ void __launch_bounds__(256) xpre_k()
{
    const int i = blockIdx.x * 256 + threadIdx.x;    // < 8*32*1024
    const int p = i & 1023;
    const int g = (i >> 10) & 31;
    const int b = i >> 15;
    const int base = ((b << 6) + (g << 1)) * PIX + p;
    d_xpre[i] = 0.5f * (d_pooled[base] + d_pooled[base + PIX]);
}

// ---------------- 3. generic fp32 GEMM, 64x64x16 tiles, 256 threads ----------------
// C[M,N] = A[M,K] * B (+bias[N]).  TRANSB: B is [N,K] (K-contig, NT). else B is [K,N] (NN).
template<bool TRANSB>
__global__ void __launch_bounds__(256) gemm_k(const float* __restrict__ A,
                                              const float* __restrict__ B,
                                              const float* __restrict__ bias,
                                              float* __restrict__ C,
                                              int M, int N, int K)
{
    __shared__ __align__(16) float As[16][68];
    __shared__ __align__(16) float Bs[16][68];
    const int tid = threadIdx.x;
    const int tx = tid & 15, ty = tid >> 4;
    const int m0 = blockIdx.y << 6, n0 = blockIdx.x << 6;
    const int lrow = tid >> 2, lkv = (tid & 3) << 2;   // A/B(NT) loader
    const int brow = tid >> 4, bcv = (tid & 15) << 2;  // B(NN) loader
    float acc[4][4] = {};

    for (int k0 = 0; k0 < K; k0 += 16) {
        float4 a4 = *(const float4*)(A + (size_t)(m0 + lrow) * K + k0 + lkv);
        As[lkv + 0][lrow] = a4.x; As[lkv + 1][lrow] = a4.y;
        As[lkv + 2][lrow] = a4.z; As[lkv + 3][lrow] = a4.w;
        if (TRANSB) {
            float4 b4 = *(const float4*)(B + (size_t)(n0 + lrow) * K + k0 + lkv);
            Bs[lkv + 0][lrow] = b4.x; Bs[lkv + 1][lrow] = b4.y;
            Bs[lkv + 2][lrow] = b4.z; Bs[lkv + 3][lrow] = b4.w;
        } else {
            float4 b4 = *(const float4*)(B + (size_t)(k0 + brow) * N + n0 + bcv);
            Bs[brow][bcv + 0] = b4.x; Bs[brow][bcv + 1] = b4.y;
            Bs[brow][bcv + 2] = b4.z; Bs[brow][bcv + 3] = b4.w;
        }
        __syncthreads();
        #pragma unroll
        for (int kk = 0; kk < 16; kk++) {
            float4 a = *(const float4*)&As[kk][ty << 2];
            float4 b = *(const float4*)&Bs[kk][tx << 2];
            acc[0][0] += a.x * b.x; acc[0][1] += a.x * b.y; acc[0][2] += a.x * b.z; acc[0][3] += a.x * b.w;
            acc[1][0] += a.y * b.x; acc[1][1] += a.y * b.y; acc[1][2] += a.y * b.z; acc[1][3] += a.y * b.w;
            acc[2][0] += a.z * b.x; acc[2][1] += a.z * b.y; acc[2][2] += a.z * b.z; acc[2][3] += a.z * b.w;
            acc[3][0] += a.w * b.x; acc[3][1] += a.w * b.y; acc[3][2] += a.w * b.z; acc[3][3] += a.w * b.w;
        }
        __syncthreads();
    }
    const float4 bb = *(const float4*)(bias + n0 + (tx << 2));
    #pragma unroll
    for (int i = 0; i < 4; i++) {
        const int m = m0 + (ty << 2) + i;
        float4 o;
        o.x = acc[i][0] + bb.x; o.y = acc[i][1] + bb.y;
        o.z = acc[i][2] + bb.z; o.w = acc[i][3] + bb.w;
        *(float4*)(C + (size_t)m * N + n0 + (tx << 2)) = o;
    }
}

// ---------------- 4. adj: logits, softmax, top-21 mask, renormalize-softmax ----------------
__global__ void __launch_bounds__(1024) adj_k()
{
    const int b = blockIdx.x;
    const int s = threadIdx.x >> 5;     // warp = one source row
    const int t = threadIdx.x & 31;     // lane = target col
    const float4* krow = (const float4*)(d_kg + (size_t)(b * GRP + s) * PQ);
    const float4* qrow = (const float4*)(d_qg + (size_t)(b * GRP + t) * PQ);
    float acc = 0.f;
    #pragma unroll 8
    for (int d = 0; d < PQ / 4; d++) {
        float4 kv = krow[d], qv = qrow[d];
        acc += kv.x * qv.x + kv.y * qv.y + kv.z * qv.z + kv.w * qv.w;
    }
    // softmax #1 over t
    float m = wmax(acc);
    float e = expf(acc - m);
    float v = e / wsum(e);
    // rank (matches lax.top_k tie order: earlier index wins)
    int rank = 0;
    #pragma unroll
    for (int j = 0; j < 32; j++) {
        float vj = __shfl_sync(0xffffffffu, v, j);
        rank += (vj > v) || (vj == v && j < t);
    }
    const bool keep = rank < KTOP;
    // softmax #2 over kept entries (input = probabilities v)
    float v2 = keep ? v : -INFINITY;
    float m2 = wmax(v2);
    float e2 = keep ? expf(v - m2) : 0.f;
    float s2 = wsum(e2);
    d_adj[(b * GRP + s) * GRP + t] = e2 / s2;
}

// ---------------- 5. av = adj @ v  (per-b [32,32]@[32,1024]) ----------------
__global__ void __launch_bounds__(256) av_k()
{
    __shared__ float adjS[GRP][GRP + 1];
    __shared__ float vS[GRP][256];
    const int b = blockIdx.x;
    const int p0 = blockIdx.y << 8;
    const int tid = threadIdx.x;
    for (int i = tid; i < GRP * GRP; i += 256)
        adjS[i >> 5][i & 31] = d_adj[b * GRP * GRP + i];
    for (int i = tid; i < GRP * 256; i += 256) {
        int g = i >> 8, pp = i & 255;
        vS[g][pp] = d_v[(size_t)(b * GRP + g) * PIX + p0 + pp];
    }
    __syncthreads();
    const int pp = tid;
    for (int s = 0; s < GRP; s++) {
        float acc = 0.f;
        #pragma unroll
        for (int t = 0; t < GRP; t++) acc += adjS[s][t] * vS[t][pp];
        d_av[(size_t)(b * GRP + s) * PIX + p0 + pp] = acc;
    }
}

// ---------------- 6. atten = softmax(key @ query) over g ----------------
__global__ void __launch_bounds__(256) atten_k()
{
    __shared__ float Qs[PQ][GRP + 1];   // transposed q2[b]: Qs[d][g]
    const int b = blockIdx.x;
    const int tid = threadIdx.x;
    for (int i = tid; i < GRP * PQ; i += 256) {
        int g = i >> 8, d = i & 255;
        Qs[d][g] = d_q2[(size_t)b * GRP * PQ + i];
    }
    __syncthreads();
    const int w = tid >> 5, g = tid & 31;
    for (int c = w; c < CHN; c += 8) {
        const float* krow = d_key + (size_t)(b * CHN + c) * PQ;
        float acc = 0.f;
        for (int d0 = 0; d0 < PQ; d0 += 32) {
            float kchunk = krow[d0 + g];
            #pragma unroll
            for (int j = 0; j < 32; j++) {
                float kv = __shfl_sync(0xffffffffu, kchunk, j);
                acc += kv * Qs[d0 + j][g];
            }
        }
        float m = wmax(acc);
        float e = expf(acc - m);
        d_atten[(b * CHN + c) * GRP + g] = e / wsum(e);
    }
}

// ---------------- 7. tu = atten @ value, stored transposed (p-major, c-minor) ----------------
__global__ void __launch_bounds__(256) tu_k()
{
    __shared__ float attS[CHN][GRP + 1];
    __shared__ float vS[GRP][128];
    const int b = blockIdx.x;
    const int p0 = blockIdx.y << 7;
    const int tid = threadIdx.x;
    for (int i = tid; i < CHN * GRP; i += 256)
        attS[i >> 5][i & 31] = d_atten[b * CHN * GRP + i];
    for (int i = tid; i < GRP * 128; i += 256) {
        int g = i >> 7, pp = i & 127;
        vS[g][pp] = d_value[(size_t)(b * GRP + g) * PIX + p0 + pp];
    }
    __syncthreads();
    const int c = tid & 63;
    const int pr = tid >> 6;
    for (int pp = pr; pp < 128; pp += 4) {
        float acc = 0.f;
        #pragma unroll
        for (int g = 0; g < GRP; g++) acc += attS[c][g] * vS[g][pp];
        d_tuT[(size_t)b * 65536 + (size_t)(p0 + pp) * 64 + c] = acc;
    }
}

// ---------------- 8. Gram partials: G[b] = T T^T, T = reshape(tuT[b],[64,1024]) ----------------
__global__ void __launch_bounds__(256) gpart_k()
{
    __shared__ float Ts[128][65];   // [k][c]
    const int b = blockIdx.x;
    const int k0 = blockIdx.y << 7;
    const int tid = threadIdx.x;
    for (int i = tid; i < 64 * 128; i += 256) {
        int c = i >> 7, k = i & 127;
        Ts[k][c] = d_tuT[(size_t)b * 65536 + (size_t)c * 1024 + k0 + k];
    }
    __syncthreads();
    const int tx = tid & 15, ty = tid >> 4;
    float acc[4][4] = {};
    for (int k = 0; k < 128; k++) {
        float a0 = Ts[k][(ty << 2) + 0], a1 = Ts[k][(ty << 2) + 1];
        float a2 = Ts[k][(ty << 2) + 2], a3 = Ts[k][(ty << 2) + 3];
        float b0 = Ts[k][(tx << 2) + 0], b1 = Ts[k][(tx << 2) + 1];
        float b2 = Ts[k][(tx << 2) + 2], b3 = Ts[k][(tx << 2) + 3];
        acc[0][0] += a0 * b0; acc[0][1] += a0 * b1; acc[0][2] += a0 * b2; acc[0][3] += a0 * b3;
        acc[1][0] += a1 * b0; acc[1][1] += a1 * b1; acc[1][2] += a1 * b2; acc[1][3] += a1 * b3;
        acc[2][0] += a2 * b0; acc[2][1] += a2 * b1; acc[2][2] += a2 * b2; acc[2][3] += a2 * b3;
        acc[3][0] += a3 * b0; acc[3][1] += a3 * b1; acc[3][2] += a3 * b2; acc[3][3] += a3 * b3;
    }
    float* dst = d_Gpart + (size_t)(b * 8 + blockIdx.y) * 4096;
    #pragma unroll
    for (int i = 0; i < 4; i++)
        #pragma unroll
        for (int j = 0; j < 4; j++)
            dst[((ty << 2) + i) * 64 + (tx << 2) + j] = acc[i][j];
}

__global__ void __launch_bounds__(256) greduce_k()
{
    const int i = blockIdx.x * 256 + threadIdx.x;    // < 8*4096
    const int b = i >> 12, e = i & 4095;
    float s = 0.f;
    #pragma unroll
    for (int kc = 0; kc < 8; kc++) s += d_Gpart[(size_t)(b * 8 + kc) * 4096 + e];
    d_G[i] = s;
}

// ---------------- 9. out = G @ x_flat  per batch ([64,64]@[64,16384]) ----------------
__global__ void __launch_bounds__(256) final_k(const float* __restrict__ x,
                                               float* __restrict__ out)
{
    __shared__ __align__(16) float GsT[64][64];   // [c2][c]
    const int b = blockIdx.y;
    const int n = (blockIdx.x << 8) + threadIdx.x;
    for (int i = threadIdx.x; i < 4096; i += 256) {
        int c2 = i >> 6, c = i & 63;
        GsT[c2][c] = d_G[b * 4096 + c * 64 + c2];
    }
    __syncthreads();
    const float* xb = x + (size_t)b * CHN * HW + n;
    float acc[64];
    #pragma unroll
    for (int c = 0; c < 64; c++) acc[c] = 0.f;
    #pragma unroll 4
    for (int c2 = 0; c2 < 64; c2++) {
        float xv = __ldg(xb + (size_t)c2 * HW);
        const float4* g4 = (const float4*)GsT[c2];
        #pragma unroll
        for (int q = 0; q < 16; q++) {
            float4 g = g4[q];
            acc[4 * q + 0] += g.x * xv; acc[4 * q + 1] += g.y * xv;
            acc[4 * q + 2] += g.z * xv; acc[4 * q + 3] += g.w * xv;
        }
    }
    float* ob = out + (size_t)b * CHN * HW + n;
    #pragma unroll
    for (int c = 0; c < 64; c++) ob[(size_t)c * HW] = acc[c];
}

// ---------------- host launcher ----------------
extern "C" void kernel_launch(void* const* d_in, const int* in_sizes, int n_in,
                              void* d_out, int out_size)
{
    (void)in_sizes; (void)n_in; (void)out_size;
    const float* x          = (const float*)d_in[0];
    const float* gcn_weight = (const float*)d_in[1];
    const float* gcn_bias   = (const float*)d_in[2];
    const float* gcn_q_w    = (const float*)d_in[3];
    const float* gcn_q_b    = (const float*)d_in[4];
    const float* gcn_k_w    = (const float*)d_in[5];
    const float* gcn_k_b    = (const float*)d_in[6];
    const float* gcn_v_w    = (const float*)d_in[7];
    const float* gcn_v_b    = (const float*)d_in[8];
    const float* q_w        = (const float*)d_in[9];
    const float* q_b        = (const float*)d_in[10];
    const float* k_w        = (const float*)d_in[11];
    const float* k_b        = (const float*)d_in[12];
    const float* v_w        = (const float*)d_in[13];
    const float* v_b        = (const float*)d_in[14];
    float* out = (float*)d_out;

    float *p_pooled, *p_xpre, *p_qg, *p_kg, *p_v, *p_av, *p_gcnout, *p_value, *p_q2, *p_key;
    cudaGetSymbolAddress((void**)&p_pooled, d_pooled);
    cudaGetSymbolAddress((void**)&p_xpre,   d_xpre);
    cudaGetSymbolAddress((void**)&p_qg,     d_qg);
    cudaGetSymbolAddress((void**)&p_kg,     d_kg);
    cudaGetSymbolAddress((void**)&p_v,      d_v);
    cudaGetSymbolAddress((void**)&p_av,     d_av);
    cudaGetSymbolAddress((void**)&p_gcnout, d_gcnout);
    cudaGetSymbolAddress((void**)&p_value,  d_value);
    cudaGetSymbolAddress((void**)&p_q2,     d_q2);
    cudaGetSymbolAddress((void**)&p_key,    d_key);

    pool_k<<<BATCH * CHN, 256>>>(x);
    xpre_k<<<(BATCH * GRP * PIX) / 256, 256>>>();

    // GCN q/k projections (NT), v projection (NT), key projection (NT)
    gemm_k<true ><<<dim3(4, 4),  256>>>(p_xpre,   gcn_q_w, gcn_q_b, p_qg,  256, 256, 1024);
    gemm_k<true ><<<dim3(4, 4),  256>>>(p_xpre,   gcn_k_w, gcn_k_b, p_kg,  256, 256, 1024);
    gemm_k<true ><<<dim3(16, 4), 256>>>(p_xpre,   gcn_v_w, gcn_v_b, p_v,   256, 1024, 1024);
    gemm_k<true ><<<dim3(4, 8),  256>>>(p_pooled, k_w,     k_b,     p_key, 512, 256, 1024);

    adj_k<<<BATCH, 1024>>>();
    av_k<<<dim3(BATCH, 4), 256>>>();

    // gcn_out = (adj@v) @ gcn_weight + gcn_bias  (NN)
    gemm_k<false><<<dim3(16, 4), 256>>>(p_av,     gcn_weight, gcn_bias, p_gcnout, 256, 1024, 1024);
    // value / query projections from gcn_out (NT)
    gemm_k<true ><<<dim3(16, 4), 256>>>(p_gcnout, v_w, v_b, p_value, 256, 1024, 1024);
    gemm_k<true ><<<dim3(4, 4),  256>>>(p_gcnout, q_w, q_b, p_q2,    256, 256, 1024);

    atten_k<<<BATCH, 256>>>();
    tu_k<<<dim3(BATCH, 8), 256>>>();
    gpart_k<<<dim3(BATCH, 8), 256>>>();
    greduce_k<<<(BATCH * 4096) / 256, 256>>>();
    final_k<<<dim3(64, BATCH), 256>>>(x, out);
}

// round 2
// speedup vs baseline: 2.2769x; 2.2769x over previous
#include <cuda_runtime.h>
#include <math.h>
#include <stdint.h>

// Problem constants
#define BATCH 8
#define CHN   64
#define PIX   1024
#define PQ    256
#define GRP   32
#define HW    16384   // 128*128
#define KTOP  21      // int(32/3*2)
#define KS    4       // split-K slices
#define KCH   256     // K per slice (K=1024 for every GEMM here)

// ---------------- scratch (static device globals; no allocation) ----------------
__device__ float d_pooled[BATCH*CHN*PIX];
__device__ float d_xpre  [BATCH*GRP*PIX];
__device__ float d_WT    [PIX*PIX];          // gcn_weight transposed
__device__ float d_qg    [BATCH*GRP*PQ];
__device__ float d_kg    [BATCH*GRP*PQ];
__device__ float d_v     [BATCH*GRP*PIX];
__device__ float d_av    [BATCH*GRP*PIX];
__device__ float d_gcnout[BATCH*GRP*PIX];
__device__ float d_value [BATCH*GRP*PIX];
__device__ float d_q2    [BATCH*GRP*PQ];
__device__ float d_key   [BATCH*CHN*PQ];
__device__ float d_atten [BATCH*CHN*GRP];
__device__ float d_tuT   [BATCH*PIX*CHN];
__device__ float d_Gpart [BATCH*8*CHN*CHN];
__device__ float d_G     [BATCH*CHN*CHN];
__device__ float d_part  [524288*KS];        // split-K partials (8 MB), reused per phase

// ---------------- warp helpers ----------------
__device__ __forceinline__ float wmax(float v) {
    #pragma unroll
    for (int o = 16; o > 0; o >>= 1) v = fmaxf(v, __shfl_xor_sync(0xffffffffu, v, o));
    return v;
}
__device__ __forceinline__ float wsum(float v) {
    #pragma unroll
    for (int o = 16; o > 0; o >>= 1) v += __shfl_xor_sync(0xffffffffu, v, o);
    return v;
}

// ---------------- 1. 4x4 mean pool ----------------
__global__ void __launch_bounds__(256) pool_k(const float* __restrict__ x)
{
    const int bc = blockIdx.x;
    const float* xp = x + (size_t)bc * HW;
    for (int p = threadIdx.x; p < PIX; p += 256) {
        const int h4 = p >> 5, w4 = p & 31;
        const float* base = xp + (h4 * 4) * 128 + w4 * 4;
        float s = 0.f;
        #pragma unroll
        for (int i = 0; i < 4; i++) {
            float4 r = *(const float4*)(base + i * 128);
            s += r.x + r.y + r.z + r.w;
        }
        d_pooled[bc * PIX + p] = s * (1.f / 16.f);
    }
}

// ---------------- 2. xpre = mean over channel pair ----------------
__global__ void __launch_bounds__(256) xpre_k()
{
    const int i = blockIdx.x * 256 + threadIdx.x;
    const int p = i & 1023;
    const int g = (i >> 10) & 31;
    const int b = i >> 15;
    const int base = ((b << 6) + (g << 1)) * PIX + p;
    d_xpre[i] = 0.5f * (d_pooled[base] + d_pooled[base + PIX]);
}

// ---------------- 3. transpose gcn_weight: WT[q][p] = W[p][q] ----------------
__global__ void __launch_bounds__(256) transW_k(const float* __restrict__ W)
{
    __shared__ float ts[32][33];
    const int bx = blockIdx.x & 31, by = blockIdx.x >> 5;
    const int tx = threadIdx.x & 31, ty = threadIdx.x >> 5;
    #pragma unroll
    for (int r = ty; r < 32; r += 8)
        ts[r][tx] = W[(size_t)(by * 32 + r) * PIX + bx * 32 + tx];
    __syncthreads();
    #pragma unroll
    for (int r = ty; r < 32; r += 8)
        d_WT[(size_t)(bx * 32 + r) * PIX + by * 32 + tx] = ts[tx][r];
}

// ---------------- 4. batched split-K NT GEMM ----------------
// Every problem: C[M,N] = A[M,1024] * B[N,1024]^T, 64x64 tiles, split-K x4.
// Partials written to Cp[ks][M*N]; bias added later in the reduce.
struct GProb {
    const float* A; const float* B; float* Cp;
    int M, N, tm, tn, tile_begin;
};
struct GBatch { GProb p[4]; int n; };

__global__ void __launch_bounds__(256) gemm_batch_k(GBatch gb)
{
    __shared__ __align__(16) float As[16][68];
    __shared__ __align__(16) float Bs[16][68];

    const int bid = blockIdx.x;
    GProb pr = gb.p[0];
    #pragma unroll
    for (int i = 1; i < 4; i++)
        if (i < gb.n && bid >= gb.p[i].tile_begin) pr = gb.p[i];

    const int local = bid - pr.tile_begin;
    const int tmn = pr.tm * pr.tn;
    const int ks = local / tmn;
    const int t = local - ks * tmn;
    const int m0 = (t / pr.tn) << 6;
    const int n0 = (t % pr.tn) << 6;

    const int tid = threadIdx.x;
    const int tx = tid & 15, ty = tid >> 4;
    const int lrow = tid >> 2, lkv = (tid & 3) << 2;

    const float* Aptr = pr.A + (size_t)(m0 + lrow) * 1024 + ks * KCH + lkv;
    const float* Bptr = pr.B + (size_t)(n0 + lrow) * 1024 + ks * KCH + lkv;

    float acc[4][4] = {};
    float4 a4 = *(const float4*)Aptr;
    float4 b4 = *(const float4*)Bptr;

    for (int c = 0; c < 16; c++) {
        As[lkv + 0][lrow] = a4.x; As[lkv + 1][lrow] = a4.y;
        As[lkv + 2][lrow] = a4.z; As[lkv + 3][lrow] = a4.w;
        Bs[lkv + 0][lrow] = b4.x; Bs[lkv + 1][lrow] = b4.y;
        Bs[lkv + 2][lrow] = b4.z; Bs[lkv + 3][lrow] = b4.w;
        __syncthreads();
        if (c < 15) {
            a4 = *(const float4*)(Aptr + (c + 1) * 16);
            b4 = *(const float4*)(Bptr + (c + 1) * 16);
        }
        #pragma unroll
        for (int kk = 0; kk < 16; kk++) {
            float4 a = *(const float4*)&As[kk][ty << 2];
            float4 b = *(const float4*)&Bs[kk][tx << 2];
            acc[0][0] += a.x * b.x; acc[0][1] += a.x * b.y; acc[0][2] += a.x * b.z; acc[0][3] += a.x * b.w;
            acc[1][0] += a.y * b.x; acc[1][1] += a.y * b.y; acc[1][2] += a.y * b.z; acc[1][3] += a.y * b.w;
            acc[2][0] += a.z * b.x; acc[2][1] += a.z * b.y; acc[2][2] += a.z * b.z; acc[2][3] += a.z * b.w;
            acc[3][0] += a.w * b.x; acc[3][1] += a.w * b.y; acc[3][2] += a.w * b.z; acc[3][3] += a.w * b.w;
        }
        __syncthreads();
    }
    float* dst = pr.Cp + (size_t)ks * pr.M * pr.N;
    #pragma unroll
    for (int i = 0; i < 4; i++) {
        const int m = m0 + (ty << 2) + i;
        *(float4*)(dst + (size_t)m * pr.N + n0 + (tx << 2)) = *(float4*)acc[i];
    }
}

// ---------------- 5. split-K reduce + bias ----------------
struct RProb {
    const float* Cp; float* C; const float* bias;
    int MN, N, elem_begin;
};
struct RBatch { RProb p[4]; int n; int total; };

__global__ void __launch_bounds__(256) reduce_batch_k(RBatch rb)
{
    const int e = blockIdx.x * 256 + threadIdx.x;
    if (e >= rb.total) return;
    RProb pr = rb.p[0];
    #pragma unroll
    for (int i = 1; i < 4; i++)
        if (i < rb.n && e >= rb.p[i].elem_begin) pr = rb.p[i];
    const int local = e - pr.elem_begin;
    const int n = local % pr.N;
    float s = 0.f;
    #pragma unroll
    for (int ks = 0; ks < KS; ks++) s += pr.Cp[(size_t)ks * pr.MN + local];
    pr.C[local] = s + pr.bias[n];
}

// ---------------- 6. fused adj (softmax/top-k/softmax) + av = adj @ v ----------------
__global__ void __launch_bounds__(1024) adjav_k()
{
    __shared__ float adjS[GRP][GRP + 1];
    const int b = blockIdx.x;
    const int tid = threadIdx.x;
    const int s = tid >> 5, t = tid & 31;
    {
        const float4* krow = (const float4*)(d_kg + (size_t)(b * GRP + s) * PQ);
        const float4* qrow = (const float4*)(d_qg + (size_t)(b * GRP + t) * PQ);
        float acc = 0.f;
        #pragma unroll 8
        for (int d = 0; d < PQ / 4; d++) {
            float4 kv = krow[d], qv = qrow[d];
            acc += kv.x * qv.x + kv.y * qv.y + kv.z * qv.z + kv.w * qv.w;
        }
        float m = wmax(acc);
        float e = expf(acc - m);
        float v = e / wsum(e);
        int rank = 0;
        #pragma unroll
        for (int j = 0; j < 32; j++) {
            float vj = __shfl_sync(0xffffffffu, v, j);
            rank += (vj > v) || (vj == v && j < t);
        }
        const bool keep = rank < KTOP;
        float v2 = keep ? v : -INFINITY;
        float m2 = wmax(v2);
        float e2 = keep ? expf(v - m2) : 0.f;
        float s2 = wsum(e2);
        adjS[s][t] = e2 / s2;
    }
    __syncthreads();
    const int p = tid;
    float vreg[GRP];
    #pragma unroll
    for (int t2 = 0; t2 < GRP; t2++)
        vreg[t2] = d_v[(size_t)(b * GRP + t2) * PIX + p];
    #pragma unroll
    for (int s2 = 0; s2 < GRP; s2++) {
        float acc = 0.f;
        #pragma unroll
        for (int t2 = 0; t2 < GRP; t2++) acc += adjS[s2][t2] * vreg[t2];
        d_av[(size_t)(b * GRP + s2) * PIX + p] = acc;
    }
}

// ---------------- 7. atten = softmax(key @ query) over g ----------------
__global__ void __launch_bounds__(256) atten_k()
{
    __shared__ float Qs[PQ][GRP + 1];
    const int b = blockIdx.x;
    const int tid = threadIdx.x;
    for (int i = tid; i < GRP * PQ; i += 256) {
        int g = i >> 8, d = i & 255;
        Qs[d][g] = d_q2[(size_t)b * GRP * PQ + i];
    }
    __syncthreads();
    const int w = tid >> 5, g = tid & 31;
    for (int c = w; c < CHN; c += 8) {
        const float* krow = d_key + (size_t)(b * CHN + c) * PQ;
        float acc = 0.f;
        for (int d0 = 0; d0 < PQ; d0 += 32) {
            float kchunk = krow[d0 + g];
            #pragma unroll
            for (int j = 0; j < 32; j++) {
                float kv = __shfl_sync(0xffffffffu, kchunk, j);
                acc += kv * Qs[d0 + j][g];
            }
        }
        float m = wmax(acc);
        float e = expf(acc - m);
        d_atten[(b * CHN + c) * GRP + g] = e / wsum(e);
    }
}

// ---------------- 8. tu = atten @ value, stored transposed ----------------
__global__ void __launch_bounds__(256) tu_k()
{
    __shared__ float attS[CHN][GRP + 1];
    __shared__ float vS[GRP][128];
    const int b = blockIdx.x;
    const int p0 = blockIdx.y << 7;
    const int tid = threadIdx.x;
    for (int i = tid; i < CHN * GRP; i += 256)
        attS[i >> 5][i & 31] = d_atten[b * CHN * GRP + i];
    for (int i = tid; i < GRP * 128; i += 256) {
        int g = i >> 7, pp = i & 127;
        vS[g][pp] = d_value[(size_t)(b * GRP + g) * PIX + p0 + pp];
    }
    __syncthreads();
    const int c = tid & 63;
    const int pr = tid >> 6;
    for (int pp = pr; pp < 128; pp += 4) {
        float acc = 0.f;
        #pragma unroll
        for (int g = 0; g < GRP; g++) acc += attS[c][g] * vS[g][pp];
        d_tuT[(size_t)b * 65536 + (size_t)(p0 + pp) * 64 + c] = acc;
    }
}

// ---------------- 9. Gram partials: G[b] = T T^T ----------------
__global__ void __launch_bounds__(256) gpart_k()
{
    __shared__ float Ts[128][65];
    const int b = blockIdx.x;
    const int k0 = blockIdx.y << 7;
    const int tid = threadIdx.x;
    for (int i = tid; i < 64 * 128; i += 256) {
        int c = i >> 7, k = i & 127;
        Ts[k][c] = d_tuT[(size_t)b * 65536 + (size_t)c * 1024 + k0 + k];
    }
    __syncthreads();
    const int tx = tid & 15, ty = tid >> 4;
    float acc[4][4] = {};
    for (int k = 0; k < 128; k++) {
        float a0 = Ts[k][(ty << 2) + 0], a1 = Ts[k][(ty << 2) + 1];
        float a2 = Ts[k][(ty << 2) + 2], a3 = Ts[k][(ty << 2) + 3];
        float b0 = Ts[k][(tx << 2) + 0], b1 = Ts[k][(tx << 2) + 1];
        float b2 = Ts[k][(tx << 2) + 2], b3 = Ts[k][(tx << 2) + 3];
        acc[0][0] += a0 * b0; acc[0][1] += a0 * b1; acc[0][2] += a0 * b2; acc[0][3] += a0 * b3;
        acc[1][0] += a1 * b0; acc[1][1] += a1 * b1; acc[1][2] += a1 * b2; acc[1][3] += a1 * b3;
        acc[2][0] += a2 * b0; acc[2][1] += a2 * b1; acc[2][2] += a2 * b2; acc[2][3] += a2 * b3;
        acc[3][0] += a3 * b0; acc[3][1] += a3 * b1; acc[3][2] += a3 * b2; acc[3][3] += a3 * b3;
    }
    float* dst = d_Gpart + (size_t)(b * 8 + blockIdx.y) * 4096;
    #pragma unroll
    for (int i = 0; i < 4; i++)
        #pragma unroll
        for (int j = 0; j < 4; j++)
            dst[((ty << 2) + i) * 64 + (tx << 2) + j] = acc[i][j];
}

__global__ void __launch_bounds__(256) greduce_k()
{
    const int i = blockIdx.x * 256 + threadIdx.x;
    const int b = i >> 12, e = i & 4095;
    float s = 0.f;
    #pragma unroll
    for (int kc = 0; kc < 8; kc++) s += d_Gpart[(size_t)(b * 8 + kc) * 4096 + e];
    d_G[i] = s;
}

// ---------------- 10. out = G @ x_flat per batch ----------------
__global__ void __launch_bounds__(256) final_k(const float* __restrict__ x,
                                               float* __restrict__ out)
{
    __shared__ __align__(16) float GsT[64][64];
    const int b = blockIdx.y;
    const int n = (blockIdx.x << 8) + threadIdx.x;
    for (int i = threadIdx.x; i < 4096; i += 256) {
        int c2 = i >> 6, c = i & 63;
        GsT[c2][c] = d_G[b * 4096 + c * 64 + c2];
    }
    __syncthreads();
    const float* xb = x + (size_t)b * CHN * HW + n;
    float acc[64];
    #pragma unroll
    for (int c = 0; c < 64; c++) acc[c] = 0.f;
    #pragma unroll 4
    for (int c2 = 0; c2 < 64; c2++) {
        float xv = __ldg(xb + (size_t)c2 * HW);
        const float4* g4 = (const float4*)GsT[c2];
        #pragma unroll
        for (int q = 0; q < 16; q++) {
            float4 g = g4[q];
            acc[4 * q + 0] += g.x * xv; acc[4 * q + 1] += g.y * xv;
            acc[4 * q + 2] += g.z * xv; acc[4 * q + 3] += g.w * xv;
        }
    }
    float* ob = out + (size_t)b * CHN * HW + n;
    #pragma unroll
    for (int c = 0; c < 64; c++) ob[(size_t)c * HW] = acc[c];
}

// ---------------- host launcher ----------------
extern "C" void kernel_launch(void* const* d_in, const int* in_sizes, int n_in,
                              void* d_out, int out_size)
{
    (void)in_sizes; (void)n_in; (void)out_size;
    const float* x          = (const float*)d_in[0];
    const float* gcn_weight = (const float*)d_in[1];
    const float* gcn_bias   = (const float*)d_in[2];
    const float* gcn_q_w    = (const float*)d_in[3];
    const float* gcn_q_b    = (const float*)d_in[4];
    const float* gcn_k_w    = (const float*)d_in[5];
    const float* gcn_k_b    = (const float*)d_in[6];
    const float* gcn_v_w    = (const float*)d_in[7];
    const float* gcn_v_b    = (const float*)d_in[8];
    const float* q_w        = (const float*)d_in[9];
    const float* q_b        = (const float*)d_in[10];
    const float* k_w        = (const float*)d_in[11];
    const float* k_b        = (const float*)d_in[12];
    const float* v_w        = (const float*)d_in[13];
    const float* v_b        = (const float*)d_in[14];
    float* out = (float*)d_out;

    float *p_pooled, *p_xpre, *p_WT, *p_qg, *p_kg, *p_v, *p_av, *p_gcnout,
          *p_value, *p_q2, *p_key, *p_part;
    cudaGetSymbolAddress((void**)&p_pooled, d_pooled);
    cudaGetSymbolAddress((void**)&p_xpre,   d_xpre);
    cudaGetSymbolAddress((void**)&p_WT,     d_WT);
    cudaGetSymbolAddress((void**)&p_qg,     d_qg);
    cudaGetSymbolAddress((void**)&p_kg,     d_kg);
    cudaGetSymbolAddress((void**)&p_v,      d_v);
    cudaGetSymbolAddress((void**)&p_av,     d_av);
    cudaGetSymbolAddress((void**)&p_gcnout, d_gcnout);
    cudaGetSymbolAddress((void**)&p_value,  d_value);
    cudaGetSymbolAddress((void**)&p_q2,     d_q2);
    cudaGetSymbolAddress((void**)&p_key,    d_key);
    cudaGetSymbolAddress((void**)&p_part,   d_part);

    transW_k<<<1024, 256>>>(gcn_weight);
    pool_k<<<BATCH * CHN, 256>>>(x);
    xpre_k<<<(BATCH * GRP * PIX) / 256, 256>>>();

    // ---- Phase 1: {qg, kg, v, key} in one batched split-K launch ----
    // tiles: qg 16, kg 16, v 64, key 32  -> x4 slices = 512 blocks
    {
        GBatch gb{};
        int off = 0, tb = 0;
        // qg: M=256, N=256
        gb.p[0] = { p_xpre, gcn_q_w, p_part + off, 256, 256, 4, 4, tb };
        off += 256 * 256 * KS; tb += 4 * 4 * KS;
        // kg
        gb.p[1] = { p_xpre, gcn_k_w, p_part + off, 256, 256, 4, 4, tb };
        off += 256 * 256 * KS; tb += 4 * 4 * KS;
        // v: M=256, N=1024
        gb.p[2] = { p_xpre, gcn_v_w, p_part + off, 256, 1024, 4, 16, tb };
        off += 256 * 1024 * KS; tb += 4 * 16 * KS;
        // key: M=512, N=256
        gb.p[3] = { p_pooled, k_w, p_part + off, 512, 256, 8, 4, tb };
        tb += 8 * 4 * KS;
        gb.n = 4;
        gemm_batch_k<<<tb, 256>>>(gb);

        RBatch rb{};
        int eb = 0; off = 0;
        rb.p[0] = { p_part + off, p_qg,  gcn_q_b, 256 * 256, 256, eb };
        off += 256 * 256 * KS; eb += 256 * 256;
        rb.p[1] = { p_part + off, p_kg,  gcn_k_b, 256 * 256, 256, eb };
        off += 256 * 256 * KS; eb += 256 * 256;
        rb.p[2] = { p_part + off, p_v,   gcn_v_b, 256 * 1024, 1024, eb };
        off += 256 * 1024 * KS; eb += 256 * 1024;
        rb.p[3] = { p_part + off, p_key, k_b, 512 * 256, 256, eb };
        eb += 512 * 256;
        rb.n = 4; rb.total = eb;
        reduce_batch_k<<<(eb + 255) / 256, 256>>>(rb);
    }

    adjav_k<<<BATCH, 1024>>>();

    // ---- Phase 2: gcnout = av @ WT ----
    {
        GBatch gb{};
        gb.p[0] = { p_av, p_WT, p_part, 256, 1024, 4, 16, 0 };
        gb.n = 1;
        gemm_batch_k<<<4 * 16 * KS, 256>>>(gb);

        RBatch rb{};
        rb.p[0] = { p_part, p_gcnout, gcn_bias, 256 * 1024, 1024, 0 };
        rb.n = 1; rb.total = 256 * 1024;
        reduce_batch_k<<<(256 * 1024) / 256, 256>>>(rb);
    }

    // ---- Phase 3: {value, q2} ----
    {
        GBatch gb{};
        int off = 0, tb = 0;
        gb.p[0] = { p_gcnout, v_w, p_part + off, 256, 1024, 4, 16, tb };
        off += 256 * 1024 * KS; tb += 4 * 16 * KS;
        gb.p[1] = { p_gcnout, q_w, p_part + off, 256, 256, 4, 4, tb };
        tb += 4 * 4 * KS;
        gb.n = 2;
        gemm_batch_k<<<tb, 256>>>(gb);

        RBatch rb{};
        int eb = 0; off = 0;
        rb.p[0] = { p_part + off, p_value, v_b, 256 * 1024, 1024, eb };
        off += 256 * 1024 * KS; eb += 256 * 1024;
        rb.p[1] = { p_part + off, p_q2, q_b, 256 * 256, 256, eb };
        eb += 256 * 256;
        rb.n = 2; rb.total = eb;
        reduce_batch_k<<<(eb + 255) / 256, 256>>>(rb);
    }

    atten_k<<<BATCH, 256>>>();
    tu_k<<<dim3(BATCH, 8), 256>>>();
    gpart_k<<<dim3(BATCH, 8), 256>>>();
    greduce_k<<<(BATCH * 4096) / 256, 256>>>();
    final_k<<<dim3(64, BATCH), 256>>>(x, out);
}

// round 3
// speedup vs baseline: 2.6151x; 1.1486x over previous
#include <cuda_runtime.h>
#include <math.h>
#include <stdint.h>

// Problem constants
#define BATCH 8
#define CHN   64
#define PIX   1024
#define PQ    256
#define GRP   32
#define HW    16384   // 128*128
#define KTOP  21      // int(32/3*2)

// ---------------- scratch (static device globals; no allocation) ----------------
__device__ float d_pooled[BATCH*CHN*PIX];
__device__ float d_xpre  [BATCH*GRP*PIX];
__device__ float d_WT    [PIX*PIX];          // gcn_weight transposed
__device__ float d_qg    [BATCH*GRP*PQ];
__device__ float d_kg    [BATCH*GRP*PQ];
__device__ float d_adj   [BATCH*GRP*GRP];
__device__ float d_v     [BATCH*GRP*PIX];
__device__ float d_av    [BATCH*GRP*PIX];
__device__ float d_gcnout[BATCH*GRP*PIX];
__device__ float d_value [BATCH*GRP*PIX];
__device__ float d_q2    [BATCH*GRP*PQ];
__device__ float d_key   [BATCH*CHN*PQ];
__device__ float d_atten [BATCH*CHN*GRP];
__device__ float d_tuT   [BATCH*PIX*CHN];
__device__ float d_Gpart [BATCH*8*CHN*CHN];
__device__ float d_G     [BATCH*CHN*CHN];
__device__ float d_part  [8388608];          // split-K partials (32 MB)

// ---------------- warp helpers ----------------
__device__ __forceinline__ float wmax(float v) {
    #pragma unroll
    for (int o = 16; o > 0; o >>= 1) v = fmaxf(v, __shfl_xor_sync(0xffffffffu, v, o));
    return v;
}
__device__ __forceinline__ float wsum(float v) {
    #pragma unroll
    for (int o = 16; o > 0; o >>= 1) v += __shfl_xor_sync(0xffffffffu, v, o);
    return v;
}

// ---------------- 1. 4x4 mean pool ----------------
__global__ void __launch_bounds__(256) pool_k(const float* __restrict__ x)
{
    const int bc = blockIdx.x;
    const float* xp = x + (size_t)bc * HW;
    for (int p = threadIdx.x; p < PIX; p += 256) {
        const int h4 = p >> 5, w4 = p & 31;
        const float* base = xp + (h4 * 4) * 128 + w4 * 4;
        float s = 0.f;
        #pragma unroll
        for (int i = 0; i < 4; i++) {
            float4 r = *(const float4*)(base + i * 128);
            s += r.x + r.y + r.z + r.w;
        }
        d_pooled[bc * PIX + p] = s * (1.f / 16.f);
    }
}

// ---------------- 2. xpre = mean over channel pair ----------------
__global__ void __launch_bounds__(256) xpre_k()
{
    const int i = blockIdx.x * 256 + threadIdx.x;
    const int p = i & 1023;
    const int g = (i >> 10) & 31;
    const int b = i >> 15;
    const int base = ((b << 6) + (g << 1)) * PIX + p;
    d_xpre[i] = 0.5f * (d_pooled[base] + d_pooled[base + PIX]);
}

// ---------------- 3. transpose gcn_weight ----------------
__global__ void __launch_bounds__(256) transW_k(const float* __restrict__ W)
{
    __shared__ float ts[32][33];
    const int bx = blockIdx.x & 31, by = blockIdx.x >> 5;
    const int tx = threadIdx.x & 31, ty = threadIdx.x >> 5;
    #pragma unroll
    for (int r = ty; r < 32; r += 8)
        ts[r][tx] = W[(size_t)(by * 32 + r) * PIX + bx * 32 + tx];
    __syncthreads();
    #pragma unroll
    for (int r = ty; r < 32; r += 8)
        d_WT[(size_t)(bx * 32 + r) * PIX + by * 32 + tx] = ts[tx][r];
}

// ---------------- 4. batched split-K NT GEMM (64x64 tiles) ----------------
struct GProb {
    const float* A; const float* B; float* Cp;
    int M, N, tm, tn, tile_begin, ksl, kch;
};
struct GBatch { GProb p[4]; int n; };

__global__ void __launch_bounds__(256) gemm_batch_k(GBatch gb)
{
    __shared__ __align__(16) float As[16][68];
    __shared__ __align__(16) float Bs[16][68];

    const int bid = blockIdx.x;
    GProb pr = gb.p[0];
    #pragma unroll
    for (int i = 1; i < 4; i++)
        if (i < gb.n && bid >= gb.p[i].tile_begin) pr = gb.p[i];

    const int local = bid - pr.tile_begin;
    const int tmn = pr.tm * pr.tn;
    const int ks = local / tmn;
    const int t = local - ks * tmn;
    const int m0 = (t / pr.tn) << 6;
    const int n0 = (t % pr.tn) << 6;

    const int tid = threadIdx.x;
    const int tx = tid & 15, ty = tid >> 4;
    const int lrow = tid >> 2, lkv = (tid & 3) << 2;

    const float* Aptr = pr.A + (size_t)(m0 + lrow) * 1024 + ks * pr.kch + lkv;
    const float* Bptr = pr.B + (size_t)(n0 + lrow) * 1024 + ks * pr.kch + lkv;
    const int nch = pr.kch >> 4;

    float acc[4][4] = {};
    float4 a4 = *(const float4*)Aptr;
    float4 b4 = *(const float4*)Bptr;

    for (int c = 0; c < nch; c++) {
        As[lkv + 0][lrow] = a4.x; As[lkv + 1][lrow] = a4.y;
        As[lkv + 2][lrow] = a4.z; As[lkv + 3][lrow] = a4.w;
        Bs[lkv + 0][lrow] = b4.x; Bs[lkv + 1][lrow] = b4.y;
        Bs[lkv + 2][lrow] = b4.z; Bs[lkv + 3][lrow] = b4.w;
        __syncthreads();
        if (c + 1 < nch) {
            a4 = *(const float4*)(Aptr + (c + 1) * 16);
            b4 = *(const float4*)(Bptr + (c + 1) * 16);
        }
        #pragma unroll
        for (int kk = 0; kk < 16; kk++) {
            float4 a = *(const float4*)&As[kk][ty << 2];
            float4 b = *(const float4*)&Bs[kk][tx << 2];
            acc[0][0] += a.x * b.x; acc[0][1] += a.x * b.y; acc[0][2] += a.x * b.z; acc[0][3] += a.x * b.w;
            acc[1][0] += a.y * b.x; acc[1][1] += a.y * b.y; acc[1][2] += a.y * b.z; acc[1][3] += a.y * b.w;
            acc[2][0] += a.z * b.x; acc[2][1] += a.z * b.y; acc[2][2] += a.z * b.z; acc[2][3] += a.z * b.w;
            acc[3][0] += a.w * b.x; acc[3][1] += a.w * b.y; acc[3][2] += a.w * b.z; acc[3][3] += a.w * b.w;
        }
        __syncthreads();
    }
    float* dst = pr.Cp + (size_t)ks * pr.M * pr.N;
    #pragma unroll
    for (int i = 0; i < 4; i++) {
        const int m = m0 + (ty << 2) + i;
        *(float4*)(dst + (size_t)m * pr.N + n0 + (tx << 2)) = *(float4*)acc[i];
    }
}

// ---------------- 5. split-K reduce + bias ----------------
struct RProb {
    const float* Cp; float* C; const float* bias;
    int MN, N, elem_begin, ksl;
};
struct RBatch { RProb p[4]; int n; int total; };

__global__ void __launch_bounds__(256) reduce_batch_k(RBatch rb)
{
    const int e = blockIdx.x * 256 + threadIdx.x;
    if (e >= rb.total) return;
    RProb pr = rb.p[0];
    #pragma unroll
    for (int i = 1; i < 4; i++)
        if (i < rb.n && e >= rb.p[i].elem_begin) pr = rb.p[i];
    const int local = e - pr.elem_begin;
    const int n = local % pr.N;
    float s = 0.f;
    #pragma unroll 4
    for (int ks = 0; ks < pr.ksl; ks++) s += pr.Cp[(size_t)ks * pr.MN + local];
    pr.C[local] = s + pr.bias[n];
}

// ---------------- 6. adj: softmax / top-21 / renorm-softmax ----------------
__global__ void __launch_bounds__(1024) adj_k()
{
    const int b = blockIdx.x;
    const int s = threadIdx.x >> 5, t = threadIdx.x & 31;
    const float4* krow = (const float4*)(d_kg + (size_t)(b * GRP + s) * PQ);
    const float4* qrow = (const float4*)(d_qg + (size_t)(b * GRP + t) * PQ);
    float acc = 0.f;
    #pragma unroll 8
    for (int d = 0; d < PQ / 4; d++) {
        float4 kv = krow[d], qv = qrow[d];
        acc += kv.x * qv.x + kv.y * qv.y + kv.z * qv.z + kv.w * qv.w;
    }
    float m = wmax(acc);
    float e = expf(acc - m);
    float v = e / wsum(e);
    int rank = 0;
    #pragma unroll
    for (int j = 0; j < 32; j++) {
        float vj = __shfl_sync(0xffffffffu, v, j);
        rank += (vj > v) || (vj == v && j < t);
    }
    const bool keep = rank < KTOP;
    float v2 = keep ? v : -INFINITY;
    float m2 = wmax(v2);
    float e2 = keep ? expf(v - m2) : 0.f;
    float s2 = wsum(e2);
    d_adj[(b * GRP + s) * GRP + t] = e2 / s2;
}

// ---------------- 7. av = adj @ v ----------------
__global__ void __launch_bounds__(256) av_k()
{
    __shared__ float adjS[GRP][GRP + 1];
    __shared__ float vS[GRP][256];
    const int b = blockIdx.x;
    const int p0 = blockIdx.y << 8;
    const int tid = threadIdx.x;
    for (int i = tid; i < GRP * GRP; i += 256)
        adjS[i >> 5][i & 31] = d_adj[b * GRP * GRP + i];
    for (int i = tid; i < GRP * 256; i += 256) {
        int g = i >> 8, pp = i & 255;
        vS[g][pp] = d_v[(size_t)(b * GRP + g) * PIX + p0 + pp];
    }
    __syncthreads();
    const int pp = tid;
    for (int s = 0; s < GRP; s++) {
        float acc = 0.f;
        #pragma unroll
        for (int t = 0; t < GRP; t++) acc += adjS[s][t] * vS[t][pp];
        d_av[(size_t)(b * GRP + s) * PIX + p0 + pp] = acc;
    }
}

// ---------------- 8. atten = softmax(key @ query) over g; grid (8b, 8cg) ----------------
__global__ void __launch_bounds__(256) atten_k()
{
    __shared__ float Qs[GRP][PQ + 4];   // Qs[g][d], padded
    const int b = blockIdx.x;
    const int cg = blockIdx.y;
    const int tid = threadIdx.x;
    for (int i = tid; i < GRP * PQ; i += 256) {
        int g = i >> 8, d = i & 255;
        Qs[g][d] = d_q2[(size_t)b * GRP * PQ + i];
    }
    __syncthreads();
    const int w = tid >> 5, g = tid & 31;
    const int c = cg * 8 + w;
    const float* krow = d_key + (size_t)(b * CHN + c) * PQ;
    float acc = 0.f;
    #pragma unroll 4
    for (int d = 0; d < PQ; d++)
        acc += __ldg(krow + d) * Qs[g][d];
    float m = wmax(acc);
    float e = expf(acc - m);
    d_atten[(b * CHN + c) * GRP + g] = e / wsum(e);
}

// ---------------- 9. tu = atten @ value, stored transposed ----------------
__global__ void __launch_bounds__(256) tu_k()
{
    __shared__ float attS[CHN][GRP + 1];
    __shared__ float vS[GRP][128];
    const int b = blockIdx.x;
    const int p0 = blockIdx.y << 7;
    const int tid = threadIdx.x;
    for (int i = tid; i < CHN * GRP; i += 256)
        attS[i >> 5][i & 31] = d_atten[b * CHN * GRP + i];
    for (int i = tid; i < GRP * 128; i += 256) {
        int g = i >> 7, pp = i & 127;
        vS[g][pp] = d_value[(size_t)(b * GRP + g) * PIX + p0 + pp];
    }
    __syncthreads();
    const int c = tid & 63;
    const int pr = tid >> 6;
    for (int pp = pr; pp < 128; pp += 4) {
        float acc = 0.f;
        #pragma unroll
        for (int g = 0; g < GRP; g++) acc += attS[c][g] * vS[g][pp];
        d_tuT[(size_t)b * 65536 + (size_t)(p0 + pp) * 64 + c] = acc;
    }
}

// ---------------- 10. Gram partials + reduce ----------------
__global__ void __launch_bounds__(256) gpart_k()
{
    __shared__ float Ts[128][65];
    const int b = blockIdx.x;
    const int k0 = blockIdx.y << 7;
    const int tid = threadIdx.x;
    for (int i = tid; i < 64 * 128; i += 256) {
        int c = i >> 7, k = i & 127;
        Ts[k][c] = d_tuT[(size_t)b * 65536 + (size_t)c * 1024 + k0 + k];
    }
    __syncthreads();
    const int tx = tid & 15, ty = tid >> 4;
    float acc[4][4] = {};
    for (int k = 0; k < 128; k++) {
        float a0 = Ts[k][(ty << 2) + 0], a1 = Ts[k][(ty << 2) + 1];
        float a2 = Ts[k][(ty << 2) + 2], a3 = Ts[k][(ty << 2) + 3];
        float b0 = Ts[k][(tx << 2) + 0], b1 = Ts[k][(tx << 2) + 1];
        float b2 = Ts[k][(tx << 2) + 2], b3 = Ts[k][(tx << 2) + 3];
        acc[0][0] += a0 * b0; acc[0][1] += a0 * b1; acc[0][2] += a0 * b2; acc[0][3] += a0 * b3;
        acc[1][0] += a1 * b0; acc[1][1] += a1 * b1; acc[1][2] += a1 * b2; acc[1][3] += a1 * b3;
        acc[2][0] += a2 * b0; acc[2][1] += a2 * b1; acc[2][2] += a2 * b2; acc[2][3] += a2 * b3;
        acc[3][0] += a3 * b0; acc[3][1] += a3 * b1; acc[3][2] += a3 * b2; acc[3][3] += a3 * b3;
    }
    float* dst = d_Gpart + (size_t)(b * 8 + blockIdx.y) * 4096;
    #pragma unroll
    for (int i = 0; i < 4; i++)
        #pragma unroll
        for (int j = 0; j < 4; j++)
            dst[((ty << 2) + i) * 64 + (tx << 2) + j] = acc[i][j];
}

__global__ void __launch_bounds__(256) greduce_k()
{
    const int i = blockIdx.x * 256 + threadIdx.x;
    const int b = i >> 12, e = i & 4095;
    float s = 0.f;
    #pragma unroll
    for (int kc = 0; kc < 8; kc++) s += d_Gpart[(size_t)(b * 8 + kc) * 4096 + e];
    d_G[i] = s;
}

// ---------------- 11. out = G @ x_flat, register-blocked 8x8 ----------------
// grid (64 pix-blocks, 8 batches), 256 thr = 8 chan-groups x 32 pix-groups
__global__ void __launch_bounds__(256) final_k(const float* __restrict__ x,
                                               float* __restrict__ out)
{
    __shared__ __align__(16) float GsT[64][64];   // [c2][c]
    const int b = blockIdx.y;
    const int tid = threadIdx.x;
    const int tc = tid >> 5;            // 0..7  -> channels tc*8..+8
    const int tp = tid & 31;            // 0..31 -> pixels tp*8..+8
    const int n0 = (blockIdx.x << 8) + (tp << 3);
    const int c0 = tc << 3;

    for (int i = tid; i < 4096; i += 256) {
        int c2 = i >> 6, c = i & 63;
        GsT[c2][c] = d_G[b * 4096 + c * 64 + c2];
    }
    __syncthreads();

    const float* xb = x + (size_t)b * CHN * HW + n0;
    float acc[8][8];
    #pragma unroll
    for (int i = 0; i < 8; i++)
        #pragma unroll
        for (int j = 0; j < 8; j++) acc[i][j] = 0.f;

    float4 nx0 = *(const float4*)(xb);
    float4 nx1 = *(const float4*)(xb + 4);
    #pragma unroll 4
    for (int c2 = 0; c2 < 64; c2++) {
        float xv[8];
        xv[0] = nx0.x; xv[1] = nx0.y; xv[2] = nx0.z; xv[3] = nx0.w;
        xv[4] = nx1.x; xv[5] = nx1.y; xv[6] = nx1.z; xv[7] = nx1.w;
        if (c2 < 63) {
            const float* nxt = xb + (size_t)(c2 + 1) * HW;
            nx0 = *(const float4*)(nxt);
            nx1 = *(const float4*)(nxt + 4);
        }
        float4 g0 = *(const float4*)&GsT[c2][c0];
        float4 g1 = *(const float4*)&GsT[c2][c0 + 4];
        float gv[8];
        gv[0] = g0.x; gv[1] = g0.y; gv[2] = g0.z; gv[3] = g0.w;
        gv[4] = g1.x; gv[5] = g1.y; gv[6] = g1.z; gv[7] = g1.w;
        #pragma unroll
        for (int i = 0; i < 8; i++)
            #pragma unroll
            for (int j = 0; j < 8; j++)
                acc[i][j] += gv[i] * xv[j];
    }

    float* ob = out + (size_t)b * CHN * HW + n0;
    #pragma unroll
    for (int i = 0; i < 8; i++) {
        float* orow = ob + (size_t)(c0 + i) * HW;
        *(float4*)(orow)     = make_float4(acc[i][0], acc[i][1], acc[i][2], acc[i][3]);
        *(float4*)(orow + 4) = make_float4(acc[i][4], acc[i][5], acc[i][6], acc[i][7]);
    }
}

// ---------------- host launcher ----------------
extern "C" void kernel_launch(void* const* d_in, const int* in_sizes, int n_in,
                              void* d_out, int out_size)
{
    (void)in_sizes; (void)n_in; (void)out_size;
    const float* x          = (const float*)d_in[0];
    const float* gcn_weight = (const float*)d_in[1];
    const float* gcn_bias   = (const float*)d_in[2];
    const float* gcn_q_w    = (const float*)d_in[3];
    const float* gcn_q_b    = (const float*)d_in[4];
    const float* gcn_k_w    = (const float*)d_in[5];
    const float* gcn_k_b    = (const float*)d_in[6];
    const float* gcn_v_w    = (const float*)d_in[7];
    const float* gcn_v_b    = (const float*)d_in[8];
    const float* q_w        = (const float*)d_in[9];
    const float* q_b        = (const float*)d_in[10];
    const float* k_w        = (const float*)d_in[11];
    const float* k_b        = (const float*)d_in[12];
    const float* v_w        = (const float*)d_in[13];
    const float* v_b        = (const float*)d_in[14];
    float* out = (float*)d_out;

    float *p_pooled, *p_xpre, *p_WT, *p_qg, *p_kg, *p_v, *p_av, *p_gcnout,
          *p_value, *p_q2, *p_key, *p_part;
    cudaGetSymbolAddress((void**)&p_pooled, d_pooled);
    cudaGetSymbolAddress((void**)&p_xpre,   d_xpre);
    cudaGetSymbolAddress((void**)&p_WT,     d_WT);
    cudaGetSymbolAddress((void**)&p_qg,     d_qg);
    cudaGetSymbolAddress((void**)&p_kg,     d_kg);
    cudaGetSymbolAddress((void**)&p_v,      d_v);
    cudaGetSymbolAddress((void**)&p_av,     d_av);
    cudaGetSymbolAddress((void**)&p_gcnout, d_gcnout);
    cudaGetSymbolAddress((void**)&p_value,  d_value);
    cudaGetSymbolAddress((void**)&p_q2,     d_q2);
    cudaGetSymbolAddress((void**)&p_key,    d_key);
    cudaGetSymbolAddress((void**)&p_part,   d_part);

    pool_k<<<BATCH * CHN, 256>>>(x);
    xpre_k<<<(BATCH * GRP * PIX) / 256, 256>>>();
    transW_k<<<1024, 256>>>(gcn_weight);

    // ---- Phase 1: {qg, kg, v, key}, split-K x8 -> 1024 blocks ----
    {
        GBatch gb{};
        int off = 0, tb = 0;
        gb.p[0] = { p_xpre, gcn_q_w, p_part + off, 256, 256, 4, 4, tb, 8, 128 };
        off += 256 * 256 * 8; tb += 4 * 4 * 8;
        gb.p[1] = { p_xpre, gcn_k_w, p_part + off, 256, 256, 4, 4, tb, 8, 128 };
        off += 256 * 256 * 8; tb += 4 * 4 * 8;
        gb.p[2] = { p_xpre, gcn_v_w, p_part + off, 256, 1024, 4, 16, tb, 8, 128 };
        off += 256 * 1024 * 8; tb += 4 * 16 * 8;
        gb.p[3] = { p_pooled, k_w, p_part + off, 512, 256, 8, 4, tb, 8, 128 };
        tb += 8 * 4 * 8;
        gb.n = 4;
        gemm_batch_k<<<tb, 256>>>(gb);

        RBatch rb{};
        int eb = 0; off = 0;
        rb.p[0] = { p_part + off, p_qg,  gcn_q_b, 256 * 256, 256, eb, 8 };
        off += 256 * 256 * 8; eb += 256 * 256;
        rb.p[1] = { p_part + off, p_kg,  gcn_k_b, 256 * 256, 256, eb, 8 };
        off += 256 * 256 * 8; eb += 256 * 256;
        rb.p[2] = { p_part + off, p_v,   gcn_v_b, 256 * 1024, 1024, eb, 8 };
        off += 256 * 1024 * 8; eb += 256 * 1024;
        rb.p[3] = { p_part + off, p_key, k_b, 512 * 256, 256, eb, 8 };
        eb += 512 * 256;
        rb.n = 4; rb.total = eb;
        reduce_batch_k<<<(eb + 255) / 256, 256>>>(rb);
    }

    adj_k<<<BATCH, 1024>>>();
    av_k<<<dim3(BATCH, 4), 256>>>();

    // ---- Phase 2: gcnout = av @ WT, split-K x8 -> 512 blocks ----
    {
        GBatch gb{};
        gb.p[0] = { p_av, p_WT, p_part, 256, 1024, 4, 16, 0, 8, 128 };
        gb.n = 1;
        gemm_batch_k<<<4 * 16 * 8, 256>>>(gb);

        RBatch rb{};
        rb.p[0] = { p_part, p_gcnout, gcn_bias, 256 * 1024, 1024, 0, 8 };
        rb.n = 1; rb.total = 256 * 1024;
        reduce_batch_k<<<(256 * 1024) / 256, 256>>>(rb);
    }

    // ---- Phase 3: {value, q2}, split-K x8 -> 640 blocks ----
    {
        GBatch gb{};
        int off = 0, tb = 0;
        gb.p[0] = { p_gcnout, v_w, p_part + off, 256, 1024, 4, 16, tb, 8, 128 };
        off += 256 * 1024 * 8; tb += 4 * 16 * 8;
        gb.p[1] = { p_gcnout, q_w, p_part + off, 256, 256, 4, 4, tb, 8, 128 };
        tb += 4 * 4 * 8;
        gb.n = 2;
        gemm_batch_k<<<tb, 256>>>(gb);

        RBatch rb{};
        int eb = 0; off = 0;
        rb.p[0] = { p_part + off, p_value, v_b, 256 * 1024, 1024, eb, 8 };
        off += 256 * 1024 * 8; eb += 256 * 1024;
        rb.p[1] = { p_part + off, p_q2, q_b, 256 * 256, 256, eb, 8 };
        eb += 256 * 256;
        rb.n = 2; rb.total = eb;
        reduce_batch_k<<<(eb + 255) / 256, 256>>>(rb);
    }

    atten_k<<<dim3(BATCH, 8), 256>>>();
    tu_k<<<dim3(BATCH, 8), 256>>>();
    gpart_k<<<dim3(BATCH, 8), 256>>>();
    greduce_k<<<(BATCH * 4096) / 256, 256>>>();
    final_k<<<dim3(64, BATCH), 256>>>(x, out);
}

// round 4
// speedup vs baseline: 2.6996x; 1.0323x over previous
#include <cuda_runtime.h>
#include <math.h>
#include <stdint.h>

// Problem constants
#define BATCH 8
#define CHN   64
#define PIX   1024
#define PQ    256
#define GRP   32
#define HW    16384   // 128*128
#define KTOP  21      // int(32/3*2)

// ---------------- scratch (static device globals; no allocation) ----------------
__device__ float d_pooled[BATCH*CHN*PIX];
__device__ float d_xpre  [BATCH*GRP*PIX];
__device__ float d_WT    [PIX*PIX];          // gcn_weight transposed
__device__ float d_qg    [BATCH*GRP*PQ];
__device__ float d_kg    [BATCH*GRP*PQ];
__device__ float d_adj   [BATCH*GRP*GRP];
__device__ float d_v     [BATCH*GRP*PIX];
__device__ float d_av    [BATCH*GRP*PIX];
__device__ float d_gcnout[BATCH*GRP*PIX];
__device__ float d_value [BATCH*GRP*PIX];
__device__ float d_q2    [BATCH*GRP*PQ];
__device__ float d_key   [BATCH*CHN*PQ];
__device__ float d_atten [BATCH*CHN*GRP];
__device__ float d_tuT   [BATCH*PIX*CHN];
__device__ float d_Gpart [BATCH*8*CHN*CHN];
__device__ float d_G     [BATCH*CHN*CHN];
__device__ float d_part  [8388608];          // split-K partials (32 MB)

// ---------------- warp helpers ----------------
__device__ __forceinline__ float wmax(float v) {
    #pragma unroll
    for (int o = 16; o > 0; o >>= 1) v = fmaxf(v, __shfl_xor_sync(0xffffffffu, v, o));
    return v;
}
__device__ __forceinline__ float wsum(float v) {
    #pragma unroll
    for (int o = 16; o > 0; o >>= 1) v += __shfl_xor_sync(0xffffffffu, v, o);
    return v;
}

// ---------------- 1. fused 4x4 mean pool + channel-pair mean ----------------
// grid = BATCH*GRP; each block handles channel pair (2g, 2g+1), writes both
// pooled rows and the xpre row.
__global__ void __launch_bounds__(256) poolxpre_k(const float* __restrict__ x)
{
    const int bg = blockIdx.x;                 // b*32+g
    const int b = bg >> 5, g = bg & 31;
    const int c0 = g << 1;
    const float* xp0 = x + ((size_t)(b * CHN + c0)) * HW;
    const float* xp1 = xp0 + HW;
    float* pl0 = d_pooled + (size_t)(b * CHN + c0) * PIX;
    float* xpr = d_xpre + (size_t)bg * PIX;
    for (int p = threadIdx.x; p < PIX; p += 256) {
        const int h4 = p >> 5, w4 = p & 31;
        const int off = (h4 * 4) * 128 + w4 * 4;
        float s0 = 0.f, s1 = 0.f;
        #pragma unroll
        for (int i = 0; i < 4; i++) {
            float4 r0 = *(const float4*)(xp0 + off + i * 128);
            float4 r1 = *(const float4*)(xp1 + off + i * 128);
            s0 += r0.x + r0.y + r0.z + r0.w;
            s1 += r1.x + r1.y + r1.z + r1.w;
        }
        pl0[p]       = s0 * (1.f / 16.f);
        pl0[PIX + p] = s1 * (1.f / 16.f);
        xpr[p] = (s0 + s1) * (1.f / 32.f);
    }
}

// ---------------- 2. transpose gcn_weight ----------------
__global__ void __launch_bounds__(256) transW_k(const float* __restrict__ W)
{
    __shared__ float ts[32][33];
    const int bx = blockIdx.x & 31, by = blockIdx.x >> 5;
    const int tx = threadIdx.x & 31, ty = threadIdx.x >> 5;
    #pragma unroll
    for (int r = ty; r < 32; r += 8)
        ts[r][tx] = W[(size_t)(by * 32 + r) * PIX + bx * 32 + tx];
    __syncthreads();
    #pragma unroll
    for (int r = ty; r < 32; r += 8)
        d_WT[(size_t)(bx * 32 + r) * PIX + by * 32 + tx] = ts[tx][r];
}

// ---------------- 3. batched split-K NT GEMM (128x128x16 tiles, 8x8 blocking) ----------------
struct GProb {
    const float* A; const float* B; float* Cp;
    int M, N, tm, tn, tile_begin, kch;
};
struct GBatch { GProb p[4]; int n; };

__global__ void __launch_bounds__(256) gemm_batch_k(GBatch gb)
{
    __shared__ __align__(16) float As[16][132];
    __shared__ __align__(16) float Bs[16][132];

    const int bid = blockIdx.x;
    GProb pr = gb.p[0];
    #pragma unroll
    for (int i = 1; i < 4; i++)
        if (i < gb.n && bid >= gb.p[i].tile_begin) pr = gb.p[i];

    const int local = bid - pr.tile_begin;
    const int tmn = pr.tm * pr.tn;
    const int ks = local / tmn;
    const int t = local - ks * tmn;
    const int m0 = (t / pr.tn) << 7;
    const int n0 = (t % pr.tn) << 7;

    const int tid = threadIdx.x;
    const int tx = tid & 15, ty = tid >> 4;
    const int ar = tid >> 1, ac = (tid & 1) << 3;   // loader: row 0..127, kcol 0/8

    const float* Aptr = pr.A + (size_t)(m0 + ar) * 1024 + ks * pr.kch + ac;
    const float* Bptr = pr.B + (size_t)(n0 + ar) * 1024 + ks * pr.kch + ac;
    const int nch = pr.kch >> 4;

    float acc[8][8] = {};
    float4 a0 = *(const float4*)Aptr, a1 = *(const float4*)(Aptr + 4);
    float4 b0 = *(const float4*)Bptr, b1 = *(const float4*)(Bptr + 4);

    for (int c = 0; c < nch; c++) {
        As[ac + 0][ar] = a0.x; As[ac + 1][ar] = a0.y; As[ac + 2][ar] = a0.z; As[ac + 3][ar] = a0.w;
        As[ac + 4][ar] = a1.x; As[ac + 5][ar] = a1.y; As[ac + 6][ar] = a1.z; As[ac + 7][ar] = a1.w;
        Bs[ac + 0][ar] = b0.x; Bs[ac + 1][ar] = b0.y; Bs[ac + 2][ar] = b0.z; Bs[ac + 3][ar] = b0.w;
        Bs[ac + 4][ar] = b1.x; Bs[ac + 5][ar] = b1.y; Bs[ac + 6][ar] = b1.z; Bs[ac + 7][ar] = b1.w;
        __syncthreads();
        if (c + 1 < nch) {
            a0 = *(const float4*)(Aptr + (c + 1) * 16);
            a1 = *(const float4*)(Aptr + (c + 1) * 16 + 4);
            b0 = *(const float4*)(Bptr + (c + 1) * 16);
            b1 = *(const float4*)(Bptr + (c + 1) * 16 + 4);
        }
        #pragma unroll
        for (int kk = 0; kk < 16; kk++) {
            float4 aA = *(const float4*)&As[kk][ty << 2];
            float4 aB = *(const float4*)&As[kk][(ty << 2) + 64];
            float4 bA = *(const float4*)&Bs[kk][tx << 2];
            float4 bB = *(const float4*)&Bs[kk][(tx << 2) + 64];
            float av[8] = { aA.x, aA.y, aA.z, aA.w, aB.x, aB.y, aB.z, aB.w };
            float bv[8] = { bA.x, bA.y, bA.z, bA.w, bB.x, bB.y, bB.z, bB.w };
            #pragma unroll
            for (int i = 0; i < 8; i++)
                #pragma unroll
                for (int j = 0; j < 8; j++)
                    acc[i][j] += av[i] * bv[j];
        }
        __syncthreads();
    }

    float* dst = pr.Cp + (size_t)ks * pr.M * pr.N;
    #pragma unroll
    for (int i = 0; i < 8; i++) {
        const int m = m0 + ((i < 4) ? ((ty << 2) + i) : (64 + (ty << 2) + i - 4));
        float* row = dst + (size_t)m * pr.N + n0;
        *(float4*)(row + (tx << 2))      = make_float4(acc[i][0], acc[i][1], acc[i][2], acc[i][3]);
        *(float4*)(row + (tx << 2) + 64) = make_float4(acc[i][4], acc[i][5], acc[i][6], acc[i][7]);
    }
}

// ---------------- 4. split-K reduce + bias (float4) ----------------
struct RProb {
    const float* Cp; float* C; const float* bias;
    int MN4, N4, elem_begin, ksl;      // in float4 units
};
struct RBatch { RProb p[4]; int n; int total; };

__global__ void __launch_bounds__(256) reduce_batch_k(RBatch rb)
{
    const int e = blockIdx.x * 256 + threadIdx.x;
    if (e >= rb.total) return;
    RProb pr = rb.p[0];
    #pragma unroll
    for (int i = 1; i < 4; i++)
        if (i < rb.n && e >= rb.p[i].elem_begin) pr = rb.p[i];
    const int local = e - pr.elem_begin;
    const int n4 = local % pr.N4;
    const float4* src = (const float4*)pr.Cp + local;
    float4 s = make_float4(0.f, 0.f, 0.f, 0.f);
    #pragma unroll 4
    for (int ks = 0; ks < pr.ksl; ks++) {
        float4 p = src[(size_t)ks * pr.MN4];
        s.x += p.x; s.y += p.y; s.z += p.z; s.w += p.w;
    }
    float4 bb = ((const float4*)pr.bias)[n4];
    s.x += bb.x; s.y += bb.y; s.z += bb.z; s.w += bb.w;
    ((float4*)pr.C)[local] = s;
}

// ---------------- 5. adj: softmax / top-21 / renorm-softmax ----------------
__global__ void __launch_bounds__(1024) adj_k()
{
    const int b = blockIdx.x;
    const int s = threadIdx.x >> 5, t = threadIdx.x & 31;
    const float4* krow = (const float4*)(d_kg + (size_t)(b * GRP + s) * PQ);
    const float4* qrow = (const float4*)(d_qg + (size_t)(b * GRP + t) * PQ);
    float acc = 0.f;
    #pragma unroll 8
    for (int d = 0; d < PQ / 4; d++) {
        float4 kv = krow[d], qv = qrow[d];
        acc += kv.x * qv.x + kv.y * qv.y + kv.z * qv.z + kv.w * qv.w;
    }
    float m = wmax(acc);
    float e = expf(acc - m);
    float v = e / wsum(e);
    int rank = 0;
    #pragma unroll
    for (int j = 0; j < 32; j++) {
        float vj = __shfl_sync(0xffffffffu, v, j);
        rank += (vj > v) || (vj == v && j < t);
    }
    const bool keep = rank < KTOP;
    float v2 = keep ? v : -INFINITY;
    float m2 = wmax(v2);
    float e2 = keep ? expf(v - m2) : 0.f;
    float s2 = wsum(e2);
    d_adj[(b * GRP + s) * GRP + t] = e2 / s2;
}

// ---------------- 6. av = adj @ v ----------------
__global__ void __launch_bounds__(256) av_k()
{
    __shared__ float adjS[GRP][GRP + 1];
    __shared__ float vS[GRP][256];
    const int b = blockIdx.x;
    const int p0 = blockIdx.y << 8;
    const int tid = threadIdx.x;
    for (int i = tid; i < GRP * GRP; i += 256)
        adjS[i >> 5][i & 31] = d_adj[b * GRP * GRP + i];
    for (int i = tid; i < GRP * 256; i += 256) {
        int g = i >> 8, pp = i & 255;
        vS[g][pp] = d_v[(size_t)(b * GRP + g) * PIX + p0 + pp];
    }
    __syncthreads();
    const int pp = tid;
    for (int s = 0; s < GRP; s++) {
        float acc = 0.f;
        #pragma unroll
        for (int t = 0; t < GRP; t++) acc += adjS[s][t] * vS[t][pp];
        d_av[(size_t)(b * GRP + s) * PIX + p0 + pp] = acc;
    }
}

// ---------------- 7. atten = softmax(key @ query) over g; grid (8b, 8cg) ----------------
__global__ void __launch_bounds__(256) atten_k()
{
    __shared__ float Qs[GRP][PQ + 4];
    const int b = blockIdx.x;
    const int cg = blockIdx.y;
    const int tid = threadIdx.x;
    for (int i = tid; i < GRP * PQ; i += 256) {
        int g = i >> 8, d = i & 255;
        Qs[g][d] = d_q2[(size_t)b * GRP * PQ + i];
    }
    __syncthreads();
    const int w = tid >> 5, g = tid & 31;
    const int c = cg * 8 + w;
    const float* krow = d_key + (size_t)(b * CHN + c) * PQ;
    float acc = 0.f;
    #pragma unroll 4
    for (int d = 0; d < PQ; d++)
        acc += __ldg(krow + d) * Qs[g][d];
    float m = wmax(acc);
    float e = expf(acc - m);
    d_atten[(b * CHN + c) * GRP + g] = e / wsum(e);
}

// ---------------- 8. tu = atten @ value, stored transposed ----------------
__global__ void __launch_bounds__(256) tu_k()
{
    __shared__ float attS[CHN][GRP + 1];
    __shared__ float vS[GRP][128];
    const int b = blockIdx.x;
    const int p0 = blockIdx.y << 7;
    const int tid = threadIdx.x;
    for (int i = tid; i < CHN * GRP; i += 256)
        attS[i >> 5][i & 31] = d_atten[b * CHN * GRP + i];
    for (int i = tid; i < GRP * 128; i += 256) {
        int g = i >> 7, pp = i & 127;
        vS[g][pp] = d_value[(size_t)(b * GRP + g) * PIX + p0 + pp];
    }
    __syncthreads();
    const int c = tid & 63;
    const int pr = tid >> 6;
    for (int pp = pr; pp < 128; pp += 4) {
        float acc = 0.f;
        #pragma unroll
        for (int g = 0; g < GRP; g++) acc += attS[c][g] * vS[g][pp];
        d_tuT[(size_t)b * 65536 + (size_t)(p0 + pp) * 64 + c] = acc;
    }
}

// ---------------- 9. Gram partials + reduce ----------------
__global__ void __launch_bounds__(256) gpart_k()
{
    __shared__ float Ts[128][65];
    const int b = blockIdx.x;
    const int k0 = blockIdx.y << 7;
    const int tid = threadIdx.x;
    for (int i = tid; i < 64 * 128; i += 256) {
        int c = i >> 7, k = i & 127;
        Ts[k][c] = d_tuT[(size_t)b * 65536 + (size_t)c * 1024 + k0 + k];
    }
    __syncthreads();
    const int tx = tid & 15, ty = tid >> 4;
    float acc[4][4] = {};
    for (int k = 0; k < 128; k++) {
        float a0 = Ts[k][(ty << 2) + 0], a1 = Ts[k][(ty << 2) + 1];
        float a2 = Ts[k][(ty << 2) + 2], a3 = Ts[k][(ty << 2) + 3];
        float b0 = Ts[k][(tx << 2) + 0], b1 = Ts[k][(tx << 2) + 1];
        float b2 = Ts[k][(tx << 2) + 2], b3 = Ts[k][(tx << 2) + 3];
        acc[0][0] += a0 * b0; acc[0][1] += a0 * b1; acc[0][2] += a0 * b2; acc[0][3] += a0 * b3;
        acc[1][0] += a1 * b0; acc[1][1] += a1 * b1; acc[1][2] += a1 * b2; acc[1][3] += a1 * b3;
        acc[2][0] += a2 * b0; acc[2][1] += a2 * b1; acc[2][2] += a2 * b2; acc[2][3] += a2 * b3;
        acc[3][0] += a3 * b0; acc[3][1] += a3 * b1; acc[3][2] += a3 * b2; acc[3][3] += a3 * b3;
    }
    float* dst = d_Gpart + (size_t)(b * 8 + blockIdx.y) * 4096;
    #pragma unroll
    for (int i = 0; i < 4; i++)
        #pragma unroll
        for (int j = 0; j < 4; j++)
            dst[((ty << 2) + i) * 64 + (tx << 2) + j] = acc[i][j];
}

__global__ void __launch_bounds__(256) greduce_k()
{
    const int i = blockIdx.x * 256 + threadIdx.x;
    const int b = i >> 12, e = i & 4095;
    float s = 0.f;
    #pragma unroll
    for (int kc = 0; kc < 8; kc++) s += d_Gpart[(size_t)(b * 8 + kc) * 4096 + e];
    d_G[i] = s;
}

// ---------------- 10. out = G @ x_flat, register-blocked 8x8 ----------------
__global__ void __launch_bounds__(256) final_k(const float* __restrict__ x,
                                               float* __restrict__ out)
{
    __shared__ __align__(16) float GsT[64][64];
    const int b = blockIdx.y;
    const int tid = threadIdx.x;
    const int tc = tid >> 5;
    const int tp = tid & 31;
    const int n0 = (blockIdx.x << 8) + (tp << 3);
    const int c0 = tc << 3;

    for (int i = tid; i < 4096; i += 256) {
        int c2 = i >> 6, c = i & 63;
        GsT[c2][c] = d_G[b * 4096 + c * 64 + c2];
    }
    __syncthreads();

    const float* xb = x + (size_t)b * CHN * HW + n0;
    float acc[8][8];
    #pragma unroll
    for (int i = 0; i < 8; i++)
        #pragma unroll
        for (int j = 0; j < 8; j++) acc[i][j] = 0.f;

    float4 nx0 = *(const float4*)(xb);
    float4 nx1 = *(const float4*)(xb + 4);
    #pragma unroll 4
    for (int c2 = 0; c2 < 64; c2++) {
        float xv[8];
        xv[0] = nx0.x; xv[1] = nx0.y; xv[2] = nx0.z; xv[3] = nx0.w;
        xv[4] = nx1.x; xv[5] = nx1.y; xv[6] = nx1.z; xv[7] = nx1.w;
        if (c2 < 63) {
            const float* nxt = xb + (size_t)(c2 + 1) * HW;
            nx0 = *(const float4*)(nxt);
            nx1 = *(const float4*)(nxt + 4);
        }
        float4 g0 = *(const float4*)&GsT[c2][c0];
        float4 g1 = *(const float4*)&GsT[c2][c0 + 4];
        float gv[8];
        gv[0] = g0.x; gv[1] = g0.y; gv[2] = g0.z; gv[3] = g0.w;
        gv[4] = g1.x; gv[5] = g1.y; gv[6] = g1.z; gv[7] = g1.w;
        #pragma unroll
        for (int i = 0; i < 8; i++)
            #pragma unroll
            for (int j = 0; j < 8; j++)
                acc[i][j] += gv[i] * xv[j];
    }

    float* ob = out + (size_t)b * CHN * HW + n0;
    #pragma unroll
    for (int i = 0; i < 8; i++) {
        float* orow = ob + (size_t)(c0 + i) * HW;
        *(float4*)(orow)     = make_float4(acc[i][0], acc[i][1], acc[i][2], acc[i][3]);
        *(float4*)(orow + 4) = make_float4(acc[i][4], acc[i][5], acc[i][6], acc[i][7]);
    }
}

// ---------------- host launcher ----------------
extern "C" void kernel_launch(void* const* d_in, const int* in_sizes, int n_in,
                              void* d_out, int out_size)
{
    (void)in_sizes; (void)n_in; (void)out_size;
    const float* x          = (const float*)d_in[0];
    const float* gcn_weight = (const float*)d_in[1];
    const float* gcn_bias   = (const float*)d_in[2];
    const float* gcn_q_w    = (const float*)d_in[3];
    const float* gcn_q_b    = (const float*)d_in[4];
    const float* gcn_k_w    = (const float*)d_in[5];
    const float* gcn_k_b    = (const float*)d_in[6];
    const float* gcn_v_w    = (const float*)d_in[7];
    const float* gcn_v_b    = (const float*)d_in[8];
    const float* q_w        = (const float*)d_in[9];
    const float* q_b        = (const float*)d_in[10];
    const float* k_w        = (const float*)d_in[11];
    const float* k_b        = (const float*)d_in[12];
    const float* v_w        = (const float*)d_in[13];
    const float* v_b        = (const float*)d_in[14];
    float* out = (float*)d_out;

    float *p_pooled, *p_xpre, *p_WT, *p_qg, *p_kg, *p_v, *p_av, *p_gcnout,
          *p_value, *p_q2, *p_key, *p_part;
    cudaGetSymbolAddress((void**)&p_pooled, d_pooled);
    cudaGetSymbolAddress((void**)&p_xpre,   d_xpre);
    cudaGetSymbolAddress((void**)&p_WT,     d_WT);
    cudaGetSymbolAddress((void**)&p_qg,     d_qg);
    cudaGetSymbolAddress((void**)&p_kg,     d_kg);
    cudaGetSymbolAddress((void**)&p_v,      d_v);
    cudaGetSymbolAddress((void**)&p_av,     d_av);
    cudaGetSymbolAddress((void**)&p_gcnout, d_gcnout);
    cudaGetSymbolAddress((void**)&p_value,  d_value);
    cudaGetSymbolAddress((void**)&p_q2,     d_q2);
    cudaGetSymbolAddress((void**)&p_key,    d_key);
    cudaGetSymbolAddress((void**)&p_part,   d_part);

    const int KSL = 8, KCHV = 128;

    poolxpre_k<<<BATCH * GRP, 256>>>(x);
    transW_k<<<1024, 256>>>(gcn_weight);

    // ---- Phase 1: {qg, kg, v, key}, 128x128 tiles, split-K x8 -> 256 blocks ----
    {
        GBatch gb{};
        int off = 0, tb = 0;
        gb.p[0] = { p_xpre, gcn_q_w, p_part + off, 256, 256, 2, 2, tb, KCHV };
        off += 256 * 256 * KSL; tb += 2 * 2 * KSL;
        gb.p[1] = { p_xpre, gcn_k_w, p_part + off, 256, 256, 2, 2, tb, KCHV };
        off += 256 * 256 * KSL; tb += 2 * 2 * KSL;
        gb.p[2] = { p_xpre, gcn_v_w, p_part + off, 256, 1024, 2, 8, tb, KCHV };
        off += 256 * 1024 * KSL; tb += 2 * 8 * KSL;
        gb.p[3] = { p_pooled, k_w, p_part + off, 512, 256, 4, 2, tb, KCHV };
        tb += 4 * 2 * KSL;
        gb.n = 4;
        gemm_batch_k<<<tb, 256>>>(gb);

        RBatch rb{};
        int eb = 0; off = 0;
        rb.p[0] = { p_part + off, p_qg,  gcn_q_b, 256 * 256 / 4, 256 / 4, eb, KSL };
        off += 256 * 256 * KSL; eb += 256 * 256 / 4;
        rb.p[1] = { p_part + off, p_kg,  gcn_k_b, 256 * 256 / 4, 256 / 4, eb, KSL };
        off += 256 * 256 * KSL; eb += 256 * 256 / 4;
        rb.p[2] = { p_part + off, p_v,   gcn_v_b, 256 * 1024 / 4, 1024 / 4, eb, KSL };
        off += 256 * 1024 * KSL; eb += 256 * 1024 / 4;
        rb.p[3] = { p_part + off, p_key, k_b, 512 * 256 / 4, 256 / 4, eb, KSL };
        eb += 512 * 256 / 4;
        rb.n = 4; rb.total = eb;
        reduce_batch_k<<<(eb + 255) / 256, 256>>>(rb);
    }

    adj_k<<<BATCH, 1024>>>();
    av_k<<<dim3(BATCH, 4), 256>>>();

    // ---- Phase 2: gcnout = av @ WT, 128 blocks ----
    {
        GBatch gb{};
        gb.p[0] = { p_av, p_WT, p_part, 256, 1024, 2, 8, 0, KCHV };
        gb.n = 1;
        gemm_batch_k<<<2 * 8 * KSL, 256>>>(gb);

        RBatch rb{};
        rb.p[0] = { p_part, p_gcnout, gcn_bias, 256 * 1024 / 4, 1024 / 4, 0, KSL };
        rb.n = 1; rb.total = 256 * 1024 / 4;
        reduce_batch_k<<<(256 * 1024 / 4 + 255) / 256, 256>>>(rb);
    }

    // ---- Phase 3: {value, q2}, 160 blocks ----
    {
        GBatch gb{};
        int off = 0, tb = 0;
        gb.p[0] = { p_gcnout, v_w, p_part + off, 256, 1024, 2, 8, tb, KCHV };
        off += 256 * 1024 * KSL; tb += 2 * 8 * KSL;
        gb.p[1] = { p_gcnout, q_w, p_part + off, 256, 256, 2, 2, tb, KCHV };
        tb += 2 * 2 * KSL;
        gb.n = 2;
        gemm_batch_k<<<tb, 256>>>(gb);

        RBatch rb{};
        int eb = 0; off = 0;
        rb.p[0] = { p_part + off, p_value, v_b, 256 * 1024 / 4, 1024 / 4, eb, KSL };
        off += 256 * 1024 * KSL; eb += 256 * 1024 / 4;
        rb.p[1] = { p_part + off, p_q2, q_b, 256 * 256 / 4, 256 / 4, eb, KSL };
        eb += 256 * 256 / 4;
        rb.n = 2; rb.total = eb;
        reduce_batch_k<<<(eb + 255) / 256, 256>>>(rb);
    }

    atten_k<<<dim3(BATCH, 8), 256>>>();
    tu_k<<<dim3(BATCH, 8), 256>>>();
    gpart_k<<<dim3(BATCH, 8), 256>>>();
    greduce_k<<<(BATCH * 4096) / 256, 256>>>();
    final_k<<<dim3(64, BATCH), 256>>>(x, out);
}

// round 5
// speedup vs baseline: 3.0015x; 1.1118x over previous
#include <cuda_runtime.h>
#include <math.h>
#include <stdint.h>

// Problem constants
#define BATCH 8
#define CHN   64
#define PIX   1024
#define PQ    256
#define GRP   32
#define HW    16384   // 128*128
#define KTOP  21      // int(32/3*2)

// ---------------- scratch (static device globals; no allocation) ----------------
__device__ float d_pooled[BATCH*CHN*PIX];
__device__ float d_xpre  [BATCH*GRP*PIX];
__device__ float d_WT    [PIX*PIX];          // gcn_weight transposed
__device__ float d_qg    [BATCH*GRP*PQ];
__device__ float d_kg    [BATCH*GRP*PQ];
__device__ float d_adj   [BATCH*GRP*GRP];
__device__ float d_v     [BATCH*GRP*PIX];
__device__ float d_av    [BATCH*GRP*PIX];
__device__ float d_gcnout[BATCH*GRP*PIX];
__device__ float d_value [BATCH*GRP*PIX];
__device__ float d_q2    [BATCH*GRP*PQ];
__device__ float d_key   [BATCH*CHN*PQ];
__device__ float d_atten [BATCH*CHN*GRP];
__device__ float d_tuT   [BATCH*PIX*CHN];
__device__ float d_Gpart [BATCH*8*CHN*CHN];
__device__ float d_G     [BATCH*CHN*CHN];
__device__ float d_part  [8388608];          // split-K partials (32 MB)

// ---------------- helpers ----------------
__device__ __forceinline__ float wmax(float v) {
    #pragma unroll
    for (int o = 16; o > 0; o >>= 1) v = fmaxf(v, __shfl_xor_sync(0xffffffffu, v, o));
    return v;
}
__device__ __forceinline__ float wsum(float v) {
    #pragma unroll
    for (int o = 16; o > 0; o >>= 1) v += __shfl_xor_sync(0xffffffffu, v, o);
    return v;
}
__device__ __forceinline__ uint32_t f2tf32(float x) {
    uint32_t r;
    asm("cvt.rna.tf32.f32 %0, %1;" : "=r"(r) : "f"(x));
    return r;
}
__device__ __forceinline__ void mma_tf32(float* d, const uint32_t* a, const uint32_t* b) {
    asm volatile(
        "mma.sync.aligned.m16n8k8.row.col.f32.tf32.tf32.f32 "
        "{%0,%1,%2,%3}, {%4,%5,%6,%7}, {%8,%9}, {%0,%1,%2,%3};\n"
        : "+f"(d[0]), "+f"(d[1]), "+f"(d[2]), "+f"(d[3])
        : "r"(a[0]), "r"(a[1]), "r"(a[2]), "r"(a[3]), "r"(b[0]), "r"(b[1]));
}

// ---------------- 1. fused 4x4 mean pool + channel-pair mean ----------------
__global__ void __launch_bounds__(256) poolxpre_k(const float* __restrict__ x)
{
    const int bg = blockIdx.x;                 // b*32+g
    const int b = bg >> 5, g = bg & 31;
    const int c0 = g << 1;
    const float* xp0 = x + ((size_t)(b * CHN + c0)) * HW;
    const float* xp1 = xp0 + HW;
    float* pl0 = d_pooled + (size_t)(b * CHN + c0) * PIX;
    float* xpr = d_xpre + (size_t)bg * PIX;
    for (int p = threadIdx.x; p < PIX; p += 256) {
        const int h4 = p >> 5, w4 = p & 31;
        const int off = (h4 * 4) * 128 + w4 * 4;
        float s0 = 0.f, s1 = 0.f;
        #pragma unroll
        for (int i = 0; i < 4; i++) {
            float4 r0 = *(const float4*)(xp0 + off + i * 128);
            float4 r1 = *(const float4*)(xp1 + off + i * 128);
            s0 += r0.x + r0.y + r0.z + r0.w;
            s1 += r1.x + r1.y + r1.z + r1.w;
        }
        pl0[p]       = s0 * (1.f / 16.f);
        pl0[PIX + p] = s1 * (1.f / 16.f);
        xpr[p] = (s0 + s1) * (1.f / 32.f);
    }
}

// ---------------- 2. transpose gcn_weight ----------------
__global__ void __launch_bounds__(256) transW_k(const float* __restrict__ W)
{
    __shared__ float ts[32][33];
    const int bx = blockIdx.x & 31, by = blockIdx.x >> 5;
    const int tx = threadIdx.x & 31, ty = threadIdx.x >> 5;
    #pragma unroll
    for (int r = ty; r < 32; r += 8)
        ts[r][tx] = W[(size_t)(by * 32 + r) * PIX + bx * 32 + tx];
    __syncthreads();
    #pragma unroll
    for (int r = ty; r < 32; r += 8)
        d_WT[(size_t)(bx * 32 + r) * PIX + by * 32 + tx] = ts[tx][r];
}

// ---------------- 3. shared problem structs ----------------
struct GProb {
    const float* A; const float* B; float* Cp;
    int M, N, tm, tn, tile_begin, kch;
};
struct GBatch { GProb p[4]; int n; };

// ---------------- 4. fp32 SIMT GEMM (64x64 tiles) — for top-k-feeding qg/kg ----------------
__global__ void __launch_bounds__(256) gemm32_k(GBatch gb)
{
    __shared__ __align__(16) float As[16][68];
    __shared__ __align__(16) float Bs[16][68];

    const int bid = blockIdx.x;
    GProb pr = gb.p[0];
    #pragma unroll
    for (int i = 1; i < 4; i++)
        if (i < gb.n && bid >= gb.p[i].tile_begin) pr = gb.p[i];

    const int local = bid - pr.tile_begin;
    const int tmn = pr.tm * pr.tn;
    const int ks = local / tmn;
    const int t = local - ks * tmn;
    const int m0 = (t / pr.tn) << 6;
    const int n0 = (t % pr.tn) << 6;

    const int tid = threadIdx.x;
    const int tx = tid & 15, ty = tid >> 4;
    const int lrow = tid >> 2, lkv = (tid & 3) << 2;

    const float* Aptr = pr.A + (size_t)(m0 + lrow) * 1024 + ks * pr.kch + lkv;
    const float* Bptr = pr.B + (size_t)(n0 + lrow) * 1024 + ks * pr.kch + lkv;
    const int nch = pr.kch >> 4;

    float acc[4][4] = {};
    float4 a4 = *(const float4*)Aptr;
    float4 b4 = *(const float4*)Bptr;

    for (int c = 0; c < nch; c++) {
        As[lkv + 0][lrow] = a4.x; As[lkv + 1][lrow] = a4.y;
        As[lkv + 2][lrow] = a4.z; As[lkv + 3][lrow] = a4.w;
        Bs[lkv + 0][lrow] = b4.x; Bs[lkv + 1][lrow] = b4.y;
        Bs[lkv + 2][lrow] = b4.z; Bs[lkv + 3][lrow] = b4.w;
        __syncthreads();
        if (c + 1 < nch) {
            a4 = *(const float4*)(Aptr + (c + 1) * 16);
            b4 = *(const float4*)(Bptr + (c + 1) * 16);
        }
        #pragma unroll
        for (int kk = 0; kk < 16; kk++) {
            float4 a = *(const float4*)&As[kk][ty << 2];
            float4 b = *(const float4*)&Bs[kk][tx << 2];
            acc[0][0] += a.x * b.x; acc[0][1] += a.x * b.y; acc[0][2] += a.x * b.z; acc[0][3] += a.x * b.w;
            acc[1][0] += a.y * b.x; acc[1][1] += a.y * b.y; acc[1][2] += a.y * b.z; acc[1][3] += a.y * b.w;
            acc[2][0] += a.z * b.x; acc[2][1] += a.z * b.y; acc[2][2] += a.z * b.z; acc[2][3] += a.z * b.w;
            acc[3][0] += a.w * b.x; acc[3][1] += a.w * b.y; acc[3][2] += a.w * b.z; acc[3][3] += a.w * b.w;
        }
        __syncthreads();
    }
    float* dst = pr.Cp + (size_t)ks * pr.M * pr.N;
    #pragma unroll
    for (int i = 0; i < 4; i++) {
        const int m = m0 + (ty << 2) + i;
        *(float4*)(dst + (size_t)m * pr.N + n0 + (tx << 2)) = *(float4*)acc[i];
    }
}

// ---------------- 5. tf32 tensor-core GEMM (128x128 tiles, NT) ----------------
// smem m-major with stride 36 (conflict-free fragment access).
__global__ void __launch_bounds__(256) gemmtc_k(GBatch gb)
{
    __shared__ uint32_t As[128][36];
    __shared__ uint32_t Bs[128][36];

    const int bid = blockIdx.x;
    GProb pr = gb.p[0];
    #pragma unroll
    for (int i = 1; i < 4; i++)
        if (i < gb.n && bid >= gb.p[i].tile_begin) pr = gb.p[i];

    const int local = bid - pr.tile_begin;
    const int tmn = pr.tm * pr.tn;
    const int ks = local / tmn;
    const int t = local - ks * tmn;
    const int m0 = (t / pr.tn) << 7;
    const int n0 = (t % pr.tn) << 7;

    const int tid = threadIdx.x;
    const int lane = tid & 31;
    const int w = tid >> 5;
    const int wm = (w & 1) << 6;        // warp m base: 0/64
    const int wn = (w >> 1) << 5;       // warp n base: 0/32/64/96

    const int lrow = tid >> 1;                  // 0..127
    const int lseg = (tid & 1) << 4;            // 0/16

    const float* Aptr = pr.A + (size_t)(m0 + lrow) * 1024 + ks * pr.kch + lseg;
    const float* Bptr = pr.B + (size_t)(n0 + lrow) * 1024 + ks * pr.kch + lseg;
    const int nchunk = pr.kch >> 5;             // chunks of 32

    float acc[4][4][4];
    #pragma unroll
    for (int i = 0; i < 4; i++)
        #pragma unroll
        for (int j = 0; j < 4; j++)
            #pragma unroll
            for (int q = 0; q < 4; q++) acc[i][j][q] = 0.f;

    const int fr = lane >> 2;       // 0..7
    const int fc = lane & 3;        // 0..3

    for (int c = 0; c < nchunk; c++) {
        // load + convert chunk [32 k] into smem
        {
            const float* ap = Aptr + c * 32;
            const float* bp = Bptr + c * 32;
            float4 av0 = *(const float4*)(ap);
            float4 av1 = *(const float4*)(ap + 4);
            float4 av2 = *(const float4*)(ap + 8);
            float4 av3 = *(const float4*)(ap + 12);
            float4 bv0 = *(const float4*)(bp);
            float4 bv1 = *(const float4*)(bp + 4);
            float4 bv2 = *(const float4*)(bp + 8);
            float4 bv3 = *(const float4*)(bp + 12);
            uint32_t* ad = &As[lrow][lseg];
            uint32_t* bd = &Bs[lrow][lseg];
            ad[0]  = f2tf32(av0.x); ad[1]  = f2tf32(av0.y); ad[2]  = f2tf32(av0.z); ad[3]  = f2tf32(av0.w);
            ad[4]  = f2tf32(av1.x); ad[5]  = f2tf32(av1.y); ad[6]  = f2tf32(av1.z); ad[7]  = f2tf32(av1.w);
            ad[8]  = f2tf32(av2.x); ad[9]  = f2tf32(av2.y); ad[10] = f2tf32(av2.z); ad[11] = f2tf32(av2.w);
            ad[12] = f2tf32(av3.x); ad[13] = f2tf32(av3.y); ad[14] = f2tf32(av3.z); ad[15] = f2tf32(av3.w);
            bd[0]  = f2tf32(bv0.x); bd[1]  = f2tf32(bv0.y); bd[2]  = f2tf32(bv0.z); bd[3]  = f2tf32(bv0.w);
            bd[4]  = f2tf32(bv1.x); bd[5]  = f2tf32(bv1.y); bd[6]  = f2tf32(bv1.z); bd[7]  = f2tf32(bv1.w);
            bd[8]  = f2tf32(bv2.x); bd[9]  = f2tf32(bv2.y); bd[10] = f2tf32(bv2.z); bd[11] = f2tf32(bv2.w);
            bd[12] = f2tf32(bv3.x); bd[13] = f2tf32(bv3.y); bd[14] = f2tf32(bv3.z); bd[15] = f2tf32(bv3.w);
        }
        __syncthreads();

        #pragma unroll
        for (int kst = 0; kst < 4; kst++) {
            const int k0 = kst << 3;
            uint32_t afr[4][4];
            #pragma unroll
            for (int mi = 0; mi < 4; mi++) {
                const int r0 = wm + (mi << 4) + fr;
                afr[mi][0] = As[r0][k0 + fc];
                afr[mi][1] = As[r0 + 8][k0 + fc];
                afr[mi][2] = As[r0][k0 + fc + 4];
                afr[mi][3] = As[r0 + 8][k0 + fc + 4];
            }
            uint32_t bfr[4][2];
            #pragma unroll
            for (int ni = 0; ni < 4; ni++) {
                const int cn = wn + (ni << 3) + fr;
                bfr[ni][0] = Bs[cn][k0 + fc];
                bfr[ni][1] = Bs[cn][k0 + fc + 4];
            }
            #pragma unroll
            for (int mi = 0; mi < 4; mi++)
                #pragma unroll
                for (int ni = 0; ni < 4; ni++)
                    mma_tf32(acc[mi][ni], afr[mi], bfr[ni]);
        }
        __syncthreads();
    }

    // epilogue -> partial buffer
    float* dst = pr.Cp + (size_t)ks * pr.M * pr.N;
    #pragma unroll
    for (int mi = 0; mi < 4; mi++) {
        const int mA = m0 + wm + (mi << 4) + fr;
        #pragma unroll
        for (int ni = 0; ni < 4; ni++) {
            const int n = n0 + wn + (ni << 3) + (fc << 1);
            *(float2*)(dst + (size_t)mA * pr.N + n)       = make_float2(acc[mi][ni][0], acc[mi][ni][1]);
            *(float2*)(dst + (size_t)(mA + 8) * pr.N + n) = make_float2(acc[mi][ni][2], acc[mi][ni][3]);
        }
    }
}

// ---------------- 6. split-K reduce + bias (float4) ----------------
struct RProb {
    const float* Cp; float* C; const float* bias;
    int MN4, N4, elem_begin, ksl;      // in float4 units
};
struct RBatch { RProb p[4]; int n; int total; };

__global__ void __launch_bounds__(256) reduce_batch_k(RBatch rb)
{
    const int e = blockIdx.x * 256 + threadIdx.x;
    if (e >= rb.total) return;
    RProb pr = rb.p[0];
    #pragma unroll
    for (int i = 1; i < 4; i++)
        if (i < rb.n && e >= rb.p[i].elem_begin) pr = rb.p[i];
    const int local = e - pr.elem_begin;
    const int n4 = local % pr.N4;
    const float4* src = (const float4*)pr.Cp + local;
    float4 s = make_float4(0.f, 0.f, 0.f, 0.f);
    #pragma unroll 4
    for (int ks = 0; ks < pr.ksl; ks++) {
        float4 p = src[(size_t)ks * pr.MN4];
        s.x += p.x; s.y += p.y; s.z += p.z; s.w += p.w;
    }
    float4 bb = ((const float4*)pr.bias)[n4];
    s.x += bb.x; s.y += bb.y; s.z += bb.z; s.w += bb.w;
    ((float4*)pr.C)[local] = s;
}

// ---------------- 7. adj: softmax / top-21 / renorm-softmax ----------------
__global__ void __launch_bounds__(1024) adj_k()
{
    const int b = blockIdx.x;
    const int s = threadIdx.x >> 5, t = threadIdx.x & 31;
    const float4* krow = (const float4*)(d_kg + (size_t)(b * GRP + s) * PQ);
    const float4* qrow = (const float4*)(d_qg + (size_t)(b * GRP + t) * PQ);
    float acc = 0.f;
    #pragma unroll 8
    for (int d = 0; d < PQ / 4; d++) {
        float4 kv = krow[d], qv = qrow[d];
        acc += kv.x * qv.x + kv.y * qv.y + kv.z * qv.z + kv.w * qv.w;
    }
    float m = wmax(acc);
    float e = expf(acc - m);
    float v = e / wsum(e);
    int rank = 0;
    #pragma unroll
    for (int j = 0; j < 32; j++) {
        float vj = __shfl_sync(0xffffffffu, v, j);
        rank += (vj > v) || (vj == v && j < t);
    }
    const bool keep = rank < KTOP;
    float v2 = keep ? v : -INFINITY;
    float m2 = wmax(v2);
    float e2 = keep ? expf(v - m2) : 0.f;
    float s2 = wsum(e2);
    d_adj[(b * GRP + s) * GRP + t] = e2 / s2;
}

// ---------------- 8. av = adj @ v ----------------
__global__ void __launch_bounds__(256) av_k()
{
    __shared__ float adjS[GRP][GRP + 1];
    __shared__ float vS[GRP][256];
    const int b = blockIdx.x;
    const int p0 = blockIdx.y << 8;
    const int tid = threadIdx.x;
    for (int i = tid; i < GRP * GRP; i += 256)
        adjS[i >> 5][i & 31] = d_adj[b * GRP * GRP + i];
    for (int i = tid; i < GRP * 256; i += 256) {
        int g = i >> 8, pp = i & 255;
        vS[g][pp] = d_v[(size_t)(b * GRP + g) * PIX + p0 + pp];
    }
    __syncthreads();
    const int pp = tid;
    for (int s = 0; s < GRP; s++) {
        float acc = 0.f;
        #pragma unroll
        for (int t = 0; t < GRP; t++) acc += adjS[s][t] * vS[t][pp];
        d_av[(size_t)(b * GRP + s) * PIX + p0 + pp] = acc;
    }
}

// ---------------- 9. atten = softmax(key @ query) over g ----------------
__global__ void __launch_bounds__(256) atten_k()
{
    __shared__ float Qs[GRP][PQ + 4];
    const int b = blockIdx.x;
    const int cg = blockIdx.y;
    const int tid = threadIdx.x;
    for (int i = tid; i < GRP * PQ; i += 256) {
        int g = i >> 8, d = i & 255;
        Qs[g][d] = d_q2[(size_t)b * GRP * PQ + i];
    }
    __syncthreads();
    const int w = tid >> 5, g = tid & 31;
    const int c = cg * 8 + w;
    const float* krow = d_key + (size_t)(b * CHN + c) * PQ;
    float acc = 0.f;
    #pragma unroll 4
    for (int d = 0; d < PQ; d++)
        acc += __ldg(krow + d) * Qs[g][d];
    float m = wmax(acc);
    float e = expf(acc - m);
    d_atten[(b * CHN + c) * GRP + g] = e / wsum(e);
}

// ---------------- 10. tu = atten @ value, stored transposed ----------------
__global__ void __launch_bounds__(256) tu_k()
{
    __shared__ float attS[CHN][GRP + 1];
    __shared__ float vS[GRP][128];
    const int b = blockIdx.x;
    const int p0 = blockIdx.y << 7;
    const int tid = threadIdx.x;
    for (int i = tid; i < CHN * GRP; i += 256)
        attS[i >> 5][i & 31] = d_atten[b * CHN * GRP + i];
    for (int i = tid; i < GRP * 128; i += 256) {
        int g = i >> 7, pp = i & 127;
        vS[g][pp] = d_value[(size_t)(b * GRP + g) * PIX + p0 + pp];
    }
    __syncthreads();
    const int c = tid & 63;
    const int pr = tid >> 6;
    for (int pp = pr; pp < 128; pp += 4) {
        float acc = 0.f;
        #pragma unroll
        for (int g = 0; g < GRP; g++) acc += attS[c][g] * vS[g][pp];
        d_tuT[(size_t)b * 65536 + (size_t)(p0 + pp) * 64 + c] = acc;
    }
}

// ---------------- 11. Gram partials + reduce ----------------
__global__ void __launch_bounds__(256) gpart_k()
{
    __shared__ float Ts[128][65];
    const int b = blockIdx.x;
    const int k0 = blockIdx.y << 7;
    const int tid = threadIdx.x;
    for (int i = tid; i < 64 * 128; i += 256) {
        int c = i >> 7, k = i & 127;
        Ts[k][c] = d_tuT[(size_t)b * 65536 + (size_t)c * 1024 + k0 + k];
    }
    __syncthreads();
    const int tx = tid & 15, ty = tid >> 4;
    float acc[4][4] = {};
    for (int k = 0; k < 128; k++) {
        float a0 = Ts[k][(ty << 2) + 0], a1 = Ts[k][(ty << 2) + 1];
        float a2 = Ts[k][(ty << 2) + 2], a3 = Ts[k][(ty << 2) + 3];
        float b0 = Ts[k][(tx << 2) + 0], b1 = Ts[k][(tx << 2) + 1];
        float b2 = Ts[k][(tx << 2) + 2], b3 = Ts[k][(tx << 2) + 3];
        acc[0][0] += a0 * b0; acc[0][1] += a0 * b1; acc[0][2] += a0 * b2; acc[0][3] += a0 * b3;
        acc[1][0] += a1 * b0; acc[1][1] += a1 * b1; acc[1][2] += a1 * b2; acc[1][3] += a1 * b3;
        acc[2][0] += a2 * b0; acc[2][1] += a2 * b1; acc[2][2] += a2 * b2; acc[2][3] += a2 * b3;
        acc[3][0] += a3 * b0; acc[3][1] += a3 * b1; acc[3][2] += a3 * b2; acc[3][3] += a3 * b3;
    }
    float* dst = d_Gpart + (size_t)(b * 8 + blockIdx.y) * 4096;
    #pragma unroll
    for (int i = 0; i < 4; i++)
        #pragma unroll
        for (int j = 0; j < 4; j++)
            dst[((ty << 2) + i) * 64 + (tx << 2) + j] = acc[i][j];
}

__global__ void __launch_bounds__(256) greduce_k()
{
    const int i = blockIdx.x * 256 + threadIdx.x;
    const int b = i >> 12, e = i & 4095;
    float s = 0.f;
    #pragma unroll
    for (int kc = 0; kc < 8; kc++) s += d_Gpart[(size_t)(b * 8 + kc) * 4096 + e];
    d_G[i] = s;
}

// ---------------- 12. out = G @ x_flat, register-blocked 8x8 ----------------
__global__ void __launch_bounds__(256) final_k(const float* __restrict__ x,
                                               float* __restrict__ out)
{
    __shared__ __align__(16) float GsT[64][64];
    const int b = blockIdx.y;
    const int tid = threadIdx.x;
    const int tc = tid >> 5;
    const int tp = tid & 31;
    const int n0 = (blockIdx.x << 8) + (tp << 3);
    const int c0 = tc << 3;

    for (int i = tid; i < 4096; i += 256) {
        int c2 = i >> 6, c = i & 63;
        GsT[c2][c] = d_G[b * 4096 + c * 64 + c2];
    }
    __syncthreads();

    const float* xb = x + (size_t)b * CHN * HW + n0;
    float acc[8][8];
    #pragma unroll
    for (int i = 0; i < 8; i++)
        #pragma unroll
        for (int j = 0; j < 8; j++) acc[i][j] = 0.f;

    float4 nx0 = *(const float4*)(xb);
    float4 nx1 = *(const float4*)(xb + 4);
    #pragma unroll 4
    for (int c2 = 0; c2 < 64; c2++) {
        float xv[8];
        xv[0] = nx0.x; xv[1] = nx0.y; xv[2] = nx0.z; xv[3] = nx0.w;
        xv[4] = nx1.x; xv[5] = nx1.y; xv[6] = nx1.z; xv[7] = nx1.w;
        if (c2 < 63) {
            const float* nxt = xb + (size_t)(c2 + 1) * HW;
            nx0 = *(const float4*)(nxt);
            nx1 = *(const float4*)(nxt + 4);
        }
        float4 g0 = *(const float4*)&GsT[c2][c0];
        float4 g1 = *(const float4*)&GsT[c2][c0 + 4];
        float gv[8];
        gv[0] = g0.x; gv[1] = g0.y; gv[2] = g0.z; gv[3] = g0.w;
        gv[4] = g1.x; gv[5] = g1.y; gv[6] = g1.z; gv[7] = g1.w;
        #pragma unroll
        for (int i = 0; i < 8; i++)
            #pragma unroll
            for (int j = 0; j < 8; j++)
                acc[i][j] += gv[i] * xv[j];
    }

    float* ob = out + (size_t)b * CHN * HW + n0;
    #pragma unroll
    for (int i = 0; i < 8; i++) {
        float* orow = ob + (size_t)(c0 + i) * HW;
        *(float4*)(orow)     = make_float4(acc[i][0], acc[i][1], acc[i][2], acc[i][3]);
        *(float4*)(orow + 4) = make_float4(acc[i][4], acc[i][5], acc[i][6], acc[i][7]);
    }
}

// ---------------- host launcher ----------------
extern "C" void kernel_launch(void* const* d_in, const int* in_sizes, int n_in,
                              void* d_out, int out_size)
{
    (void)in_sizes; (void)n_in; (void)out_size;
    const float* x          = (const float*)d_in[0];
    const float* gcn_weight = (const float*)d_in[1];
    const float* gcn_bias   = (const float*)d_in[2];
    const float* gcn_q_w    = (const float*)d_in[3];
    const float* gcn_q_b    = (const float*)d_in[4];
    const float* gcn_k_w    = (const float*)d_in[5];
    const float* gcn_k_b    = (const float*)d_in[6];
    const float* gcn_v_w    = (const float*)d_in[7];
    const float* gcn_v_b    = (const float*)d_in[8];
    const float* q_w        = (const float*)d_in[9];
    const float* q_b        = (const float*)d_in[10];
    const float* k_w        = (const float*)d_in[11];
    const float* k_b        = (const float*)d_in[12];
    const float* v_w        = (const float*)d_in[13];
    const float* v_b        = (const float*)d_in[14];
    float* out = (float*)d_out;

    float *p_pooled, *p_xpre, *p_WT, *p_qg, *p_kg, *p_v, *p_av, *p_gcnout,
          *p_value, *p_q2, *p_key, *p_part;
    cudaGetSymbolAddress((void**)&p_pooled, d_pooled);
    cudaGetSymbolAddress((void**)&p_xpre,   d_xpre);
    cudaGetSymbolAddress((void**)&p_WT,     d_WT);
    cudaGetSymbolAddress((void**)&p_qg,     d_qg);
    cudaGetSymbolAddress((void**)&p_kg,     d_kg);
    cudaGetSymbolAddress((void**)&p_v,      d_v);
    cudaGetSymbolAddress((void**)&p_av,     d_av);
    cudaGetSymbolAddress((void**)&p_gcnout, d_gcnout);
    cudaGetSymbolAddress((void**)&p_value,  d_value);
    cudaGetSymbolAddress((void**)&p_q2,     d_q2);
    cudaGetSymbolAddress((void**)&p_key,    d_key);
    cudaGetSymbolAddress((void**)&p_part,   d_part);

    const int KSL = 8, KCHV = 128;

    poolxpre_k<<<BATCH * GRP, 256>>>(x);
    transW_k<<<1024, 256>>>(gcn_weight);

    // ---- Phase 1a: {qg, kg} fp32 (feeds top-k; precision-critical), 64x64 tiles ----
    {
        GBatch gb{};
        int off = 0, tb = 0;
        gb.p[0] = { p_xpre, gcn_q_w, p_part + off, 256, 256, 4, 4, tb, KCHV };
        off += 256 * 256 * KSL; tb += 4 * 4 * KSL;
        gb.p[1] = { p_xpre, gcn_k_w, p_part + off, 256, 256, 4, 4, tb, KCHV };
        tb += 4 * 4 * KSL;
        gb.n = 2;
        gemm32_k<<<tb, 256>>>(gb);
    }
    // ---- Phase 1b: {v, key} tf32 tensor cores, 128x128 tiles ----
    {
        GBatch gb{};
        int off = 2 * 256 * 256 * KSL, tb = 0;
        gb.p[0] = { p_xpre, gcn_v_w, p_part + off, 256, 1024, 2, 8, tb, KCHV };
        off += 256 * 1024 * KSL; tb += 2 * 8 * KSL;
        gb.p[1] = { p_pooled, k_w, p_part + off, 512, 256, 4, 2, tb, KCHV };
        tb += 4 * 2 * KSL;
        gb.n = 2;
        gemmtc_k<<<tb, 256>>>(gb);
    }
    // ---- Phase 1 reduce (all four) ----
    {
        RBatch rb{};
        int eb = 0, off = 0;
        rb.p[0] = { p_part + off, p_qg,  gcn_q_b, 256 * 256 / 4, 256 / 4, eb, KSL };
        off += 256 * 256 * KSL; eb += 256 * 256 / 4;
        rb.p[1] = { p_part + off, p_kg,  gcn_k_b, 256 * 256 / 4, 256 / 4, eb, KSL };
        off += 256 * 256 * KSL; eb += 256 * 256 / 4;
        rb.p[2] = { p_part + off, p_v,   gcn_v_b, 256 * 1024 / 4, 1024 / 4, eb, KSL };
        off += 256 * 1024 * KSL; eb += 256 * 1024 / 4;
        rb.p[3] = { p_part + off, p_key, k_b, 512 * 256 / 4, 256 / 4, eb, KSL };
        eb += 512 * 256 / 4;
        rb.n = 4; rb.total = eb;
        reduce_batch_k<<<(eb + 255) / 256, 256>>>(rb);
    }

    adj_k<<<BATCH, 1024>>>();
    av_k<<<dim3(BATCH, 4), 256>>>();

    // ---- Phase 2: gcnout = av @ WT (tf32) ----
    {
        GBatch gb{};
        gb.p[0] = { p_av, p_WT, p_part, 256, 1024, 2, 8, 0, KCHV };
        gb.n = 1;
        gemmtc_k<<<2 * 8 * KSL, 256>>>(gb);

        RBatch rb{};
        rb.p[0] = { p_part, p_gcnout, gcn_bias, 256 * 1024 / 4, 1024 / 4, 0, KSL };
        rb.n = 1; rb.total = 256 * 1024 / 4;
        reduce_batch_k<<<(256 * 1024 / 4 + 255) / 256, 256>>>(rb);
    }

    // ---- Phase 3: {value, q2} (tf32) ----
    {
        GBatch gb{};
        int off = 0, tb = 0;
        gb.p[0] = { p_gcnout, v_w, p_part + off, 256, 1024, 2, 8, tb, KCHV };
        off += 256 * 1024 * KSL; tb += 2 * 8 * KSL;
        gb.p[1] = { p_gcnout, q_w, p_part + off, 256, 256, 2, 2, tb, KCHV };
        tb += 2 * 2 * KSL;
        gb.n = 2;
        gemmtc_k<<<tb, 256>>>(gb);

        RBatch rb{};
        int eb = 0; off = 0;
        rb.p[0] = { p_part + off, p_value, v_b, 256 * 1024 / 4, 1024 / 4, eb, KSL };
        off += 256 * 1024 * KSL; eb += 256 * 1024 / 4;
        rb.p[1] = { p_part + off, p_q2, q_b, 256 * 256 / 4, 256 / 4, eb, KSL };
        eb += 256 * 256 / 4;
        rb.n = 2; rb.total = eb;
        reduce_batch_k<<<(eb + 255) / 256, 256>>>(rb);
    }

    atten_k<<<dim3(BATCH, 8), 256>>>();
    tu_k<<<dim3(BATCH, 8), 256>>>();
    gpart_k<<<dim3(BATCH, 8), 256>>>();
    greduce_k<<<(BATCH * 4096) / 256, 256>>>();
    final_k<<<dim3(64, BATCH), 256>>>(x, out);
}

// round 7
// speedup vs baseline: 3.4543x; 1.1509x over previous
#include <cuda_runtime.h>
#include <math.h>
#include <stdint.h>

// Problem constants
#define BATCH 8
#define CHN   64
#define PIX   1024
#define PQ    256
#define GRP   32
#define HW    16384   // 128*128
#define KTOP  21      // int(32/3*2)

// ---------------- scratch (static device globals; no allocation) ----------------
__device__ float d_pooled[BATCH*CHN*PIX];
__device__ float d_xpre  [BATCH*GRP*PIX];
__device__ float d_WT    [PIX*PIX];          // gcn_weight transposed
__device__ float d_qg    [BATCH*GRP*PQ];
__device__ float d_kg    [BATCH*GRP*PQ];
__device__ float d_adj   [BATCH*GRP*GRP];
__device__ float d_v     [BATCH*GRP*PIX];
__device__ float d_av    [BATCH*GRP*PIX];
__device__ float d_gcnout[BATCH*GRP*PIX];
__device__ float d_value [BATCH*GRP*PIX];
__device__ float d_q2    [BATCH*GRP*PQ];
__device__ float d_key   [BATCH*CHN*PQ];
__device__ float d_atten [BATCH*CHN*GRP];
__device__ float d_tuT   [BATCH*PIX*CHN];
__device__ float d_Gpart [BATCH*8*CHN*CHN];
__device__ float d_G     [BATCH*CHN*CHN];
__device__ float d_part  [8388608];          // split-K partials (32 MB)

// ---------------- helpers ----------------
__device__ __forceinline__ float wmax(float v) {
    #pragma unroll
    for (int o = 16; o > 0; o >>= 1) v = fmaxf(v, __shfl_xor_sync(0xffffffffu, v, o));
    return v;
}
__device__ __forceinline__ float wsum(float v) {
    #pragma unroll
    for (int o = 16; o > 0; o >>= 1) v += __shfl_xor_sync(0xffffffffu, v, o);
    return v;
}
__device__ __forceinline__ uint32_t f2tf32(float x) {
    uint32_t r;
    asm("cvt.rna.tf32.f32 %0, %1;" : "=r"(r) : "f"(x));
    return r;
}
__device__ __forceinline__ void mma_tf32(float* d, const uint32_t* a, const uint32_t* b) {
    asm volatile(
        "mma.sync.aligned.m16n8k8.row.col.f32.tf32.tf32.f32 "
        "{%0,%1,%2,%3}, {%4,%5,%6,%7}, {%8,%9}, {%0,%1,%2,%3};\n"
        : "+f"(d[0]), "+f"(d[1]), "+f"(d[2]), "+f"(d[3])
        : "r"(a[0]), "r"(a[1]), "r"(a[2]), "r"(a[3]), "r"(b[0]), "r"(b[1]));
}

// ---------------- 1. fused 4x4 mean pool + channel-pair mean ----------------
__global__ void __launch_bounds__(256) poolxpre_k(const float* __restrict__ x)
{
    const int bg = blockIdx.x;                 // b*32+g
    const int b = bg >> 5, g = bg & 31;
    const int c0 = g << 1;
    const float* xp0 = x + ((size_t)(b * CHN + c0)) * HW;
    const float* xp1 = xp0 + HW;
    float* pl0 = d_pooled + (size_t)(b * CHN + c0) * PIX;
    float* xpr = d_xpre + (size_t)bg * PIX;
    for (int p = threadIdx.x; p < PIX; p += 256) {
        const int h4 = p >> 5, w4 = p & 31;
        const int off = (h4 * 4) * 128 + w4 * 4;
        float s0 = 0.f, s1 = 0.f;
        #pragma unroll
        for (int i = 0; i < 4; i++) {
            float4 r0 = *(const float4*)(xp0 + off + i * 128);
            float4 r1 = *(const float4*)(xp1 + off + i * 128);
            s0 += r0.x + r0.y + r0.z + r0.w;
            s1 += r1.x + r1.y + r1.z + r1.w;
        }
        pl0[p]       = s0 * (1.f / 16.f);
        pl0[PIX + p] = s1 * (1.f / 16.f);
        xpr[p] = (s0 + s1) * (1.f / 32.f);
    }
}

// ---------------- 2. transpose gcn_weight ----------------
__global__ void __launch_bounds__(256) transW_k(const float* __restrict__ W)
{
    __shared__ float ts[32][33];
    const int bx = blockIdx.x & 31, by = blockIdx.x >> 5;
    const int tx = threadIdx.x & 31, ty = threadIdx.x >> 5;
    #pragma unroll
    for (int r = ty; r < 32; r += 8)
        ts[r][tx] = W[(size_t)(by * 32 + r) * PIX + bx * 32 + tx];
    __syncthreads();
    #pragma unroll
    for (int r = ty; r < 32; r += 8)
        d_WT[(size_t)(bx * 32 + r) * PIX + by * 32 + tx] = ts[tx][r];
}

// ---------------- 3. shared problem structs ----------------
struct GProb {
    const float* A; const float* B; float* Cp;
    int M, N, tm, tn, tile_begin, kch;
};
struct GBatch { GProb p[4]; int n; };

// ---------------- 4. fp32 SIMT GEMM (64x64 tiles) — for top-k-feeding qg/kg ----------------
__global__ void __launch_bounds__(256) gemm32_k(GBatch gb)
{
    __shared__ __align__(16) float As[16][68];
    __shared__ __align__(16) float Bs[16][68];

    const int bid = blockIdx.x;
    GProb pr = gb.p[0];
    #pragma unroll
    for (int i = 1; i < 4; i++)
        if (i < gb.n && bid >= gb.p[i].tile_begin) pr = gb.p[i];

    const int local = bid - pr.tile_begin;
    const int tmn = pr.tm * pr.tn;
    const int ks = local / tmn;
    const int t = local - ks * tmn;
    const int m0 = (t / pr.tn) << 6;
    const int n0 = (t % pr.tn) << 6;

    const int tid = threadIdx.x;
    const int tx = tid & 15, ty = tid >> 4;
    const int lrow = tid >> 2, lkv = (tid & 3) << 2;

    const float* Aptr = pr.A + (size_t)(m0 + lrow) * 1024 + ks * pr.kch + lkv;
    const float* Bptr = pr.B + (size_t)(n0 + lrow) * 1024 + ks * pr.kch + lkv;
    const int nch = pr.kch >> 4;

    float acc[4][4] = {};
    float4 a4 = *(const float4*)Aptr;
    float4 b4 = *(const float4*)Bptr;

    for (int c = 0; c < nch; c++) {
        As[lkv + 0][lrow] = a4.x; As[lkv + 1][lrow] = a4.y;
        As[lkv + 2][lrow] = a4.z; As[lkv + 3][lrow] = a4.w;
        Bs[lkv + 0][lrow] = b4.x; Bs[lkv + 1][lrow] = b4.y;
        Bs[lkv + 2][lrow] = b4.z; Bs[lkv + 3][lrow] = b4.w;
        __syncthreads();
        if (c + 1 < nch) {
            a4 = *(const float4*)(Aptr + (c + 1) * 16);
            b4 = *(const float4*)(Bptr + (c + 1) * 16);
        }
        #pragma unroll
        for (int kk = 0; kk < 16; kk++) {
            float4 a = *(const float4*)&As[kk][ty << 2];
            float4 b = *(const float4*)&Bs[kk][tx << 2];
            acc[0][0] += a.x * b.x; acc[0][1] += a.x * b.y; acc[0][2] += a.x * b.z; acc[0][3] += a.x * b.w;
            acc[1][0] += a.y * b.x; acc[1][1] += a.y * b.y; acc[1][2] += a.y * b.z; acc[1][3] += a.y * b.w;
            acc[2][0] += a.z * b.x; acc[2][1] += a.z * b.y; acc[2][2] += a.z * b.z; acc[2][3] += a.z * b.w;
            acc[3][0] += a.w * b.x; acc[3][1] += a.w * b.y; acc[3][2] += a.w * b.z; acc[3][3] += a.w * b.w;
        }
        __syncthreads();
    }
    float* dst = pr.Cp + (size_t)ks * pr.M * pr.N;
    #pragma unroll
    for (int i = 0; i < 4; i++) {
        const int m = m0 + (ty << 2) + i;
        *(float4*)(dst + (size_t)m * pr.N + n0 + (tx << 2)) = *(float4*)acc[i];
    }
}

// ---------------- 5. tf32 tensor-core GEMM (128x128 tiles, NT, reg-prefetch) ----------------
__global__ void __launch_bounds__(256) gemmtc_k(GBatch gb)
{
    __shared__ uint32_t As[128][36];
    __shared__ uint32_t Bs[128][36];

    const int bid = blockIdx.x;
    GProb pr = gb.p[0];
    #pragma unroll
    for (int i = 1; i < 4; i++)
        if (i < gb.n && bid >= gb.p[i].tile_begin) pr = gb.p[i];

    const int local = bid - pr.tile_begin;
    const int tmn = pr.tm * pr.tn;
    const int ks = local / tmn;
    const int t = local - ks * tmn;
    const int m0 = (t / pr.tn) << 7;
    const int n0 = (t % pr.tn) << 7;

    const int tid = threadIdx.x;
    const int lane = tid & 31;
    const int w = tid >> 5;
    const int wm = (w & 1) << 6;        // warp m base: 0/64
    const int wn = (w >> 1) << 5;       // warp n base: 0/32/64/96

    const int lrow = tid >> 1;                  // 0..127
    const int lseg = (tid & 1) << 4;            // 0/16

    const float* Aptr = pr.A + (size_t)(m0 + lrow) * 1024 + ks * pr.kch + lseg;
    const float* Bptr = pr.B + (size_t)(n0 + lrow) * 1024 + ks * pr.kch + lseg;
    const int nchunk = pr.kch >> 5;             // chunks of 32

    float acc[4][4][4];
    #pragma unroll
    for (int i = 0; i < 4; i++)
        #pragma unroll
        for (int j = 0; j < 4; j++)
            #pragma unroll
            for (int q = 0; q < 4; q++) acc[i][j][q] = 0.f;

    const int fr = lane >> 2;       // 0..7
    const int fc = lane & 3;        // 0..3

    // register prefetch of chunk 0
    float4 av0 = *(const float4*)(Aptr);
    float4 av1 = *(const float4*)(Aptr + 4);
    float4 av2 = *(const float4*)(Aptr + 8);
    float4 av3 = *(const float4*)(Aptr + 12);
    float4 bv0 = *(const float4*)(Bptr);
    float4 bv1 = *(const float4*)(Bptr + 4);
    float4 bv2 = *(const float4*)(Bptr + 8);
    float4 bv3 = *(const float4*)(Bptr + 12);

    for (int c = 0; c < nchunk; c++) {
        {
            uint32_t* ad = &As[lrow][lseg];
            uint32_t* bd = &Bs[lrow][lseg];
            ad[0]  = f2tf32(av0.x); ad[1]  = f2tf32(av0.y); ad[2]  = f2tf32(av0.z); ad[3]  = f2tf32(av0.w);
            ad[4]  = f2tf32(av1.x); ad[5]  = f2tf32(av1.y); ad[6]  = f2tf32(av1.z); ad[7]  = f2tf32(av1.w);
            ad[8]  = f2tf32(av2.x); ad[9]  = f2tf32(av2.y); ad[10] = f2tf32(av2.z); ad[11] = f2tf32(av2.w);
            ad[12] = f2tf32(av3.x); ad[13] = f2tf32(av3.y); ad[14] = f2tf32(av3.z); ad[15] = f2tf32(av3.w);
            bd[0]  = f2tf32(bv0.x); bd[1]  = f2tf32(bv0.y); bd[2]  = f2tf32(bv0.z); bd[3]  = f2tf32(bv0.w);
            bd[4]  = f2tf32(bv1.x); bd[5]  = f2tf32(bv1.y); bd[6]  = f2tf32(bv1.z); bd[7]  = f2tf32(bv1.w);
            bd[8]  = f2tf32(bv2.x); bd[9]  = f2tf32(bv2.y); bd[10] = f2tf32(bv2.z); bd[11] = f2tf32(bv2.w);
            bd[12] = f2tf32(bv3.x); bd[13] = f2tf32(bv3.y); bd[14] = f2tf32(bv3.z); bd[15] = f2tf32(bv3.w);
        }
        __syncthreads();
        if (c + 1 < nchunk) {
            const float* ap = Aptr + (c + 1) * 32;
            const float* bp = Bptr + (c + 1) * 32;
            av0 = *(const float4*)(ap);      av1 = *(const float4*)(ap + 4);
            av2 = *(const float4*)(ap + 8);  av3 = *(const float4*)(ap + 12);
            bv0 = *(const float4*)(bp);      bv1 = *(const float4*)(bp + 4);
            bv2 = *(const float4*)(bp + 8);  bv3 = *(const float4*)(bp + 12);
        }

        #pragma unroll
        for (int kst = 0; kst < 4; kst++) {
            const int k0 = kst << 3;
            uint32_t afr[4][4];
            #pragma unroll
            for (int mi = 0; mi < 4; mi++) {
                const int r0 = wm + (mi << 4) + fr;
                afr[mi][0] = As[r0][k0 + fc];
                afr[mi][1] = As[r0 + 8][k0 + fc];
                afr[mi][2] = As[r0][k0 + fc + 4];
                afr[mi][3] = As[r0 + 8][k0 + fc + 4];
            }
            uint32_t bfr[4][2];
            #pragma unroll
            for (int ni = 0; ni < 4; ni++) {
                const int cn = wn + (ni << 3) + fr;
                bfr[ni][0] = Bs[cn][k0 + fc];
                bfr[ni][1] = Bs[cn][k0 + fc + 4];
            }
            #pragma unroll
            for (int mi = 0; mi < 4; mi++)
                #pragma unroll
                for (int ni = 0; ni < 4; ni++)
                    mma_tf32(acc[mi][ni], afr[mi], bfr[ni]);
        }
        __syncthreads();
    }

    // epilogue -> partial buffer
    float* dst = pr.Cp + (size_t)ks * pr.M * pr.N;
    #pragma unroll
    for (int mi = 0; mi < 4; mi++) {
        const int mA = m0 + wm + (mi << 4) + fr;
        #pragma unroll
        for (int ni = 0; ni < 4; ni++) {
            const int n = n0 + wn + (ni << 3) + (fc << 1);
            *(float2*)(dst + (size_t)mA * pr.N + n)       = make_float2(acc[mi][ni][0], acc[mi][ni][1]);
            *(float2*)(dst + (size_t)(mA + 8) * pr.N + n) = make_float2(acc[mi][ni][2], acc[mi][ni][3]);
        }
    }
}

// ---------------- 6. split-K reduce + bias (float4) ----------------
struct RProb {
    const float* Cp; float* C; const float* bias;
    int MN4, N4, elem_begin, ksl;      // in float4 units
};
struct RBatch { RProb p[4]; int n; int total; };

__global__ void __launch_bounds__(256) reduce_batch_k(RBatch rb)
{
    const int e = blockIdx.x * 256 + threadIdx.x;
    if (e >= rb.total) return;
    RProb pr = rb.p[0];
    #pragma unroll
    for (int i = 1; i < 4; i++)
        if (i < rb.n && e >= rb.p[i].elem_begin) pr = rb.p[i];
    const int local = e - pr.elem_begin;
    const int n4 = local % pr.N4;
    const float4* src = (const float4*)pr.Cp + local;
    float4 s = make_float4(0.f, 0.f, 0.f, 0.f);
    #pragma unroll 4
    for (int ks = 0; ks < pr.ksl; ks++) {
        float4 p = src[(size_t)ks * pr.MN4];
        s.x += p.x; s.y += p.y; s.z += p.z; s.w += p.w;
    }
    float4 bb = ((const float4*)pr.bias)[n4];
    s.x += bb.x; s.y += bb.y; s.z += bb.z; s.w += bb.w;
    ((float4*)pr.C)[local] = s;
}

// ---------------- 7. adj: softmax / top-21 / renorm-softmax ----------------
__global__ void __launch_bounds__(1024) adj_k()
{
    const int b = blockIdx.x;
    const int s = threadIdx.x >> 5, t = threadIdx.x & 31;
    const float4* krow = (const float4*)(d_kg + (size_t)(b * GRP + s) * PQ);
    const float4* qrow = (const float4*)(d_qg + (size_t)(b * GRP + t) * PQ);
    float acc = 0.f;
    #pragma unroll 8
    for (int d = 0; d < PQ / 4; d++) {
        float4 kv = krow[d], qv = qrow[d];
        acc += kv.x * qv.x + kv.y * qv.y + kv.z * qv.z + kv.w * qv.w;
    }
    float m = wmax(acc);
    float e = expf(acc - m);
    float v = e / wsum(e);
    int rank = 0;
    #pragma unroll
    for (int j = 0; j < 32; j++) {
        float vj = __shfl_sync(0xffffffffu, v, j);
        rank += (vj > v) || (vj == v && j < t);
    }
    const bool keep = rank < KTOP;
    float v2 = keep ? v : -INFINITY;
    float m2 = wmax(v2);
    float e2 = keep ? expf(v - m2) : 0.f;
    float s2 = wsum(e2);
    d_adj[(b * GRP + s) * GRP + t] = e2 / s2;
}

// ---------------- 8. av = adj @ v ----------------
__global__ void __launch_bounds__(256) av_k()
{
    __shared__ float adjS[GRP][GRP + 1];
    __shared__ float vS[GRP][256];
    const int b = blockIdx.x;
    const int p0 = blockIdx.y << 8;
    const int tid = threadIdx.x;
    for (int i = tid; i < GRP * GRP; i += 256)
        adjS[i >> 5][i & 31] = d_adj[b * GRP * GRP + i];
    for (int i = tid; i < GRP * 256; i += 256) {
        int g = i >> 8, pp = i & 255;
        vS[g][pp] = d_v[(size_t)(b * GRP + g) * PIX + p0 + pp];
    }
    __syncthreads();
    const int pp = tid;
    for (int s = 0; s < GRP; s++) {
        float acc = 0.f;
        #pragma unroll
        for (int t = 0; t < GRP; t++) acc += adjS[s][t] * vS[t][pp];
        d_av[(size_t)(b * GRP + s) * PIX + p0 + pp] = acc;
    }
}

// ---------------- 9. atten = softmax(key @ query) over g ----------------
__global__ void __launch_bounds__(256) atten_k()
{
    __shared__ float Qs[GRP][PQ + 4];
    const int b = blockIdx.x;
    const int cg = blockIdx.y;
    const int tid = threadIdx.x;
    for (int i = tid; i < GRP * PQ; i += 256) {
        int g = i >> 8, d = i & 255;
        Qs[g][d] = d_q2[(size_t)b * GRP * PQ + i];
    }
    __syncthreads();
    const int w = tid >> 5, g = tid & 31;
    const int c = cg * 8 + w;
    const float* krow = d_key + (size_t)(b * CHN + c) * PQ;
    float acc = 0.f;
    #pragma unroll 4
    for (int d = 0; d < PQ; d++)
        acc += __ldg(krow + d) * Qs[g][d];
    float m = wmax(acc);
    float e = expf(acc - m);
    d_atten[(b * CHN + c) * GRP + g] = e / wsum(e);
}

// ---------------- 10. tu = atten @ value, stored transposed ----------------
__global__ void __launch_bounds__(256) tu_k()
{
    __shared__ float attS[CHN][GRP + 1];
    __shared__ float vS[GRP][128];
    const int b = blockIdx.x;
    const int p0 = blockIdx.y << 7;
    const int tid = threadIdx.x;
    for (int i = tid; i < CHN * GRP; i += 256)
        attS[i >> 5][i & 31] = d_atten[b * CHN * GRP + i];
    for (int i = tid; i < GRP * 128; i += 256) {
        int g = i >> 7, pp = i & 127;
        vS[g][pp] = d_value[(size_t)(b * GRP + g) * PIX + p0 + pp];
    }
    __syncthreads();
    const int c = tid & 63;
    const int pr = tid >> 6;
    for (int pp = pr; pp < 128; pp += 4) {
        float acc = 0.f;
        #pragma unroll
        for (int g = 0; g < GRP; g++) acc += attS[c][g] * vS[g][pp];
        d_tuT[(size_t)b * 65536 + (size_t)(p0 + pp) * 64 + c] = acc;
    }
}

// ---------------- 11. Gram partials + reduce ----------------
__global__ void __launch_bounds__(256) gpart_k()
{
    __shared__ float Ts[128][65];
    const int b = blockIdx.x;
    const int k0 = blockIdx.y << 7;
    const int tid = threadIdx.x;
    for (int i = tid; i < 64 * 128; i += 256) {
        int c = i >> 7, k = i & 127;
        Ts[k][c] = d_tuT[(size_t)b * 65536 + (size_t)c * 1024 + k0 + k];
    }
    __syncthreads();
    const int tx = tid & 15, ty = tid >> 4;
    float acc[4][4] = {};
    for (int k = 0; k < 128; k++) {
        float a0 = Ts[k][(ty << 2) + 0], a1 = Ts[k][(ty << 2) + 1];
        float a2 = Ts[k][(ty << 2) + 2], a3 = Ts[k][(ty << 2) + 3];
        float b0 = Ts[k][(tx << 2) + 0], b1 = Ts[k][(tx << 2) + 1];
        float b2 = Ts[k][(tx << 2) + 2], b3 = Ts[k][(tx << 2) + 3];
        acc[0][0] += a0 * b0; acc[0][1] += a0 * b1; acc[0][2] += a0 * b2; acc[0][3] += a0 * b3;
        acc[1][0] += a1 * b0; acc[1][1] += a1 * b1; acc[1][2] += a1 * b2; acc[1][3] += a1 * b3;
        acc[2][0] += a2 * b0; acc[2][1] += a2 * b1; acc[2][2] += a2 * b2; acc[2][3] += a2 * b3;
        acc[3][0] += a3 * b0; acc[3][1] += a3 * b1; acc[3][2] += a3 * b2; acc[3][3] += a3 * b3;
    }
    float* dst = d_Gpart + (size_t)(b * 8 + blockIdx.y) * 4096;
    #pragma unroll
    for (int i = 0; i < 4; i++)
        #pragma unroll
        for (int j = 0; j < 4; j++)
            dst[((ty << 2) + i) * 64 + (tx << 2) + j] = acc[i][j];
}

__global__ void __launch_bounds__(256) greduce_k()
{
    const int i = blockIdx.x * 256 + threadIdx.x;
    const int b = i >> 12, e = i & 4095;
    float s = 0.f;
    #pragma unroll
    for (int kc = 0; kc < 8; kc++) s += d_Gpart[(size_t)(b * 8 + kc) * 4096 + e];
    d_G[i] = s;
}

// ---------------- 12. out = G @ x_flat — tf32 tensor cores ----------------
// grid (64 n-tiles of 256 px, 8 batches), 256 thr = 8 warps (32 cols each).
// A = G (64x64, symmetric) staged as tf32 in smem [64][68] (stride 68:
// bank = (fr*4+fc)&31, all 32 distinct -> conflict-free); B fragments loaded
// directly from global x (coalesced: 4 k-rows x 8 consecutive n per load).
__global__ void __launch_bounds__(256) finaltc_k(const float* __restrict__ x,
                                                 float* __restrict__ out)
{
    __shared__ uint32_t Gs[64][68];
    const int b = blockIdx.y;
    const int tid = threadIdx.x;
    const int lane = tid & 31, w = tid >> 5;
    const int fr = lane >> 2, fc = lane & 3;

    for (int i = tid; i < 4096; i += 256)
        Gs[i >> 6][i & 63] = f2tf32(d_G[b * 4096 + i]);
    __syncthreads();

    const int ng = (blockIdx.x << 8) + (w << 5);   // warp's global col base
    const float* xb = x + (size_t)b * CHN * HW;

    float acc[4][4][4];
    #pragma unroll
    for (int i = 0; i < 4; i++)
        #pragma unroll
        for (int j = 0; j < 4; j++)
            #pragma unroll
            for (int q = 0; q < 4; q++) acc[i][j][q] = 0.f;

    uint32_t bcur[4][2], bnxt[4][2];
    #pragma unroll
    for (int ni = 0; ni < 4; ni++) {
        const int n = ng + (ni << 3) + fr;
        bcur[ni][0] = f2tf32(__ldg(xb + (size_t)fc * HW + n));
        bcur[ni][1] = f2tf32(__ldg(xb + (size_t)(fc + 4) * HW + n));
        bnxt[ni][0] = 0; bnxt[ni][1] = 0;
    }

    #pragma unroll
    for (int kst = 0; kst < 8; kst++) {
        const int k0 = kst << 3;
        if (kst < 7) {
            #pragma unroll
            for (int ni = 0; ni < 4; ni++) {
                const int n = ng + (ni << 3) + fr;
                bnxt[ni][0] = f2tf32(__ldg(xb + (size_t)(k0 + 8 + fc) * HW + n));
                bnxt[ni][1] = f2tf32(__ldg(xb + (size_t)(k0 + 12 + fc) * HW + n));
            }
        }
        #pragma unroll
        for (int mi = 0; mi < 4; mi++) {
            uint32_t a[4];
            const int m0 = (mi << 4) + fr;
            a[0] = Gs[m0][k0 + fc];
            a[1] = Gs[m0 + 8][k0 + fc];
            a[2] = Gs[m0][k0 + fc + 4];
            a[3] = Gs[m0 + 8][k0 + fc + 4];
            #pragma unroll
            for (int ni = 0; ni < 4; ni++)
                mma_tf32(acc[mi][ni], a, bcur[ni]);
        }
        #pragma unroll
        for (int ni = 0; ni < 4; ni++) {
            bcur[ni][0] = bnxt[ni][0];
            bcur[ni][1] = bnxt[ni][1];
        }
    }

    float* ob = out + (size_t)b * CHN * HW;
    #pragma unroll
    for (int mi = 0; mi < 4; mi++) {
        const int m = (mi << 4) + fr;
        #pragma unroll
        for (int ni = 0; ni < 4; ni++) {
            const int n = ng + (ni << 3) + (fc << 1);
            *(float2*)(ob + (size_t)m * HW + n)       = make_float2(acc[mi][ni][0], acc[mi][ni][1]);
            *(float2*)(ob + (size_t)(m + 8) * HW + n) = make_float2(acc[mi][ni][2], acc[mi][ni][3]);
        }
    }
}

// ---------------- host launcher ----------------
extern "C" void kernel_launch(void* const* d_in, const int* in_sizes, int n_in,
                              void* d_out, int out_size)
{
    (void)in_sizes; (void)n_in; (void)out_size;
    const float* x          = (const float*)d_in[0];
    const float* gcn_weight = (const float*)d_in[1];
    const float* gcn_bias   = (const float*)d_in[2];
    const float* gcn_q_w    = (const float*)d_in[3];
    const float* gcn_q_b    = (const float*)d_in[4];
    const float* gcn_k_w    = (const float*)d_in[5];
    const float* gcn_k_b    = (const float*)d_in[6];
    const float* gcn_v_w    = (const float*)d_in[7];
    const float* gcn_v_b    = (const float*)d_in[8];
    const float* q_w        = (const float*)d_in[9];
    const float* q_b        = (const float*)d_in[10];
    const float* k_w        = (const float*)d_in[11];
    const float* k_b        = (const float*)d_in[12];
    const float* v_w        = (const float*)d_in[13];
    const float* v_b        = (const float*)d_in[14];
    float* out = (float*)d_out;

    float *p_pooled, *p_xpre, *p_WT, *p_qg, *p_kg, *p_v, *p_av, *p_gcnout,
          *p_value, *p_q2, *p_key, *p_part;
    cudaGetSymbolAddress((void**)&p_pooled, d_pooled);
    cudaGetSymbolAddress((void**)&p_xpre,   d_xpre);
    cudaGetSymbolAddress((void**)&p_WT,     d_WT);
    cudaGetSymbolAddress((void**)&p_qg,     d_qg);
    cudaGetSymbolAddress((void**)&p_kg,     d_kg);
    cudaGetSymbolAddress((void**)&p_v,      d_v);
    cudaGetSymbolAddress((void**)&p_av,     d_av);
    cudaGetSymbolAddress((void**)&p_gcnout, d_gcnout);
    cudaGetSymbolAddress((void**)&p_value,  d_value);
    cudaGetSymbolAddress((void**)&p_q2,     d_q2);
    cudaGetSymbolAddress((void**)&p_key,    d_key);
    cudaGetSymbolAddress((void**)&p_part,   d_part);

    poolxpre_k<<<BATCH * GRP, 256>>>(x);
    transW_k<<<1024, 256>>>(gcn_weight);

    // ---- Phase 1a: {qg, kg} fp32 (feeds top-k), 64x64 tiles, KS=8 ----
    {
        GBatch gb{};
        int off = 0, tb = 0;
        gb.p[0] = { p_xpre, gcn_q_w, p_part + off, 256, 256, 4, 4, tb, 128 };
        off += 256 * 256 * 8; tb += 4 * 4 * 8;
        gb.p[1] = { p_xpre, gcn_k_w, p_part + off, 256, 256, 4, 4, tb, 128 };
        tb += 4 * 4 * 8;
        gb.n = 2;
        gemm32_k<<<tb, 256>>>(gb);
    }
    // ---- Phase 1b: {v, key} tf32, 128x128 tiles, KS=4 ----
    {
        GBatch gb{};
        int off = 2 * 256 * 256 * 8, tb = 0;
        gb.p[0] = { p_xpre, gcn_v_w, p_part + off, 256, 1024, 2, 8, tb, 256 };
        off += 256 * 1024 * 4; tb += 2 * 8 * 4;
        gb.p[1] = { p_pooled, k_w, p_part + off, 512, 256, 4, 2, tb, 256 };
        tb += 4 * 2 * 4;
        gb.n = 2;
        gemmtc_k<<<tb, 256>>>(gb);
    }
    // ---- Phase 1 reduce ----
    {
        RBatch rb{};
        int eb = 0, off = 0;
        rb.p[0] = { p_part + off, p_qg,  gcn_q_b, 256 * 256 / 4, 256 / 4, eb, 8 };
        off += 256 * 256 * 8; eb += 256 * 256 / 4;
        rb.p[1] = { p_part + off, p_kg,  gcn_k_b, 256 * 256 / 4, 256 / 4, eb, 8 };
        off += 256 * 256 * 8; eb += 256 * 256 / 4;
        rb.p[2] = { p_part + off, p_v,   gcn_v_b, 256 * 1024 / 4, 1024 / 4, eb, 4 };
        off += 256 * 1024 * 4; eb += 256 * 1024 / 4;
        rb.p[3] = { p_part + off, p_key, k_b, 512 * 256 / 4, 256 / 4, eb, 4 };
        eb += 512 * 256 / 4;
        rb.n = 4; rb.total = eb;
        reduce_batch_k<<<(eb + 255) / 256, 256>>>(rb);
    }

    adj_k<<<BATCH, 1024>>>();
    av_k<<<dim3(BATCH, 4), 256>>>();

    // ---- Phase 2: gcnout = av @ WT (tf32), KS=8 ----
    {
        GBatch gb{};
        gb.p[0] = { p_av, p_WT, p_part, 256, 1024, 2, 8, 0, 128 };
        gb.n = 1;
        gemmtc_k<<<2 * 8 * 8, 256>>>(gb);

        RBatch rb{};
        rb.p[0] = { p_part, p_gcnout, gcn_bias, 256 * 1024 / 4, 1024 / 4, 0, 8 };
        rb.n = 1; rb.total = 256 * 1024 / 4;
        reduce_batch_k<<<(256 * 1024 / 4 + 255) / 256, 256>>>(rb);
    }

    // ---- Phase 3: {value, q2} (tf32), KS=8 ----
    {
        GBatch gb{};
        int off = 0, tb = 0;
        gb.p[0] = { p_gcnout, v_w, p_part + off, 256, 1024, 2, 8, tb, 128 };
        off += 256 * 1024 * 8; tb += 2 * 8 * 8;
        gb.p[1] = { p_gcnout, q_w, p_part + off, 256, 256, 2, 2, tb, 128 };
        tb += 2 * 2 * 8;
        gb.n = 2;
        gemmtc_k<<<tb, 256>>>(gb);

        RBatch rb{};
        int eb = 0; off = 0;
        rb.p[0] = { p_part + off, p_value, v_b, 256 * 1024 / 4, 1024 / 4, eb, 8 };
        off += 256 * 1024 * 8; eb += 256 * 1024 / 4;
        rb.p[1] = { p_part + off, p_q2, q_b, 256 * 256 / 4, 256 / 4, eb, 8 };
        eb += 256 * 256 / 4;
        rb.n = 2; rb.total = eb;
        reduce_batch_k<<<(eb + 255) / 256, 256>>>(rb);
    }

    atten_k<<<dim3(BATCH, 8), 256>>>();
    tu_k<<<dim3(BATCH, 8), 256>>>();
    gpart_k<<<dim3(BATCH, 8), 256>>>();
    greduce_k<<<(BATCH * 4096) / 256, 256>>>();
    finaltc_k<<<dim3(64, BATCH), 256>>>(x, out);
}